// round 11
// baseline (speedup 1.0000x reference)
#include <cuda_runtime.h>
#include <cuda_fp16.h>

#define NN 50000
#define DD 128
#define EE 1600000
#define KATT 20
#define SCAN_TILE 4096
#define SCAN_BLOCKS ((NN + SCAN_TILE - 1) / SCAN_TILE)

// ---------------- scratch (static device allocations) ----------------
__device__ __half g_qkv[NN * 384];
__device__ __half g_attn[NN * DD];
__device__ __half g_a[NN * DD];
__device__ __half g_tmp[NN * 512];
__device__ __half g_h[NN * DD];
__device__ __half g_h2[NN * DD];
__device__ __half g_neigh[NN * DD];
__device__ __half g_hx[NN * DD];
__device__ int   g_deg[NN];
__device__ int   g_off[NN + 1];
__device__ int   g_cnt[NN];
__device__ int   g_csr[EE];
__device__ int   g_bsum[SCAN_BLOCKS];

// converted (fp16, pair-permuted) weights; fp32 permuted biases/LN params
__device__ __half g_wqkv[3 * 384 * 128];
__device__ __half g_wout[3 * 128 * 128];
__device__ __half g_wf1 [3 * 512 * 128];
__device__ __half g_wf2 [3 * 128 * 512];
__device__ __half g_wg  [2 * 128 * 256];
__device__ float g_bqkv[3 * 384];
__device__ float g_bout[3 * 128];
__device__ float g_bf1 [3 * 512];
__device__ float g_bf2 [3 * 128];
__device__ float g_l1g [3 * 128];
__device__ float g_l1b [3 * 128];
__device__ float g_l2g [3 * 128];
__device__ float g_l2b [3 * 128];
__device__ float g_bg  [2 * 128];
__device__ float g_gg  [2 * 128];
__device__ float g_gb  [2 * 128];

// ---------------- helpers ----------------
// within-16 column PAIR permutation (logical -> physical):
// pair p (cols 2p,2p+1) -> np = ((p&3)<<1)|(p>>2). Keeps pairs adjacent so
// thread t's mma k-halves {2t,2t+1} and {2t+8,2t+9} form one 8B word.
__device__ __forceinline__ int gperm16(int i) {
    const int p  = (i >> 1) & 7;
    const int o  = i & 1;
    const int np = ((p & 3) << 1) | (p >> 2);
    return (i & ~15) | (np << 1) | o;
}
// inverse (physical -> logical)
__device__ __forceinline__ int igperm16(int c) {
    const int np = (c >> 1) & 7;
    const int o  = c & 1;
    const int p  = ((np >> 1) & 3) | ((np & 1) << 2);
    return (c & ~15) | (p << 1) | o;
}

__device__ __forceinline__ void mma_f16(float c[4], unsigned a0, unsigned a1,
                                        unsigned a2, unsigned a3,
                                        unsigned b0, unsigned b1) {
    asm("mma.sync.aligned.m16n8k16.row.col.f32.f16.f16.f32 "
        "{%0,%1,%2,%3}, {%4,%5,%6,%7}, {%8,%9}, {%0,%1,%2,%3};\n"
        : "+f"(c[0]), "+f"(c[1]), "+f"(c[2]), "+f"(c[3])
        : "r"(a0), "r"(a1), "r"(a2), "r"(a3), "r"(b0), "r"(b1));
}

__device__ __forceinline__ void cp16(void* sdst, const void* gsrc, int sz) {
    unsigned s = (unsigned)__cvta_generic_to_shared(sdst);
    asm volatile("cp.async.cg.shared.global [%0], [%1], 16, %2;\n"
                 :: "r"(s), "l"(gsrc), "r"(sz));
}
__device__ __forceinline__ void cp_commit() {
    asm volatile("cp.async.commit_group;\n");
}
__device__ __forceinline__ void cp_wait1() {
    asm volatile("cp.async.wait_group 1;\n");
}
__device__ __forceinline__ void cp_wait0() {
    asm volatile("cp.async.wait_group 0;\n");
}

// ---------------- parameter conversion ----------------
struct PEnt { const float* s; void* d; int rows; int cols; int mode; };
struct PTab { PEnt e[32]; };

__global__ void param_conv(PTab t, int n) {
    const int ei = blockIdx.y;
    if (ei >= n) return;
    const PEnt en = t.e[ei];
    const int total = en.rows * en.cols;
    for (int i = blockIdx.x * blockDim.x + threadIdx.x; i < total;
         i += gridDim.x * blockDim.x) {
        if (en.mode == 0) {           // matrix: permute both dims, fp16
            const int r = i / en.cols, c = i % en.cols;
            ((__half*)en.d)[(size_t)gperm16(r) * en.cols + gperm16(c)] =
                __float2half_rn(en.s[i]);
        } else {                      // vector: permute only, fp32
            ((float*)en.d)[gperm16(i)] = en.s[i];
        }
    }
}

__global__ void conv_x(const float* __restrict__ x, __half* __restrict__ o) {
    const int i = blockIdx.x * blockDim.x + threadIdx.x;
    if (i < NN * 128) {
        const int r = i >> 7, c = i & 127;
        o[(r << 7) + gperm16(c)] = __float2half_rn(x[i]);
    }
}

// ---------------- fused FP16 tensor-core GEMM (cp.async pipelined) ----------------
// All operands fp16 in permuted world. Block 128x128, 8 warps (4m x 2n),
// warp tile 32x64, BK=64 halves, 2-stage cp.async. Smem row stride 160B
// (conflict-free 8B fragment loads). Accum fp32, epilogue fp32.
// OMODE 1: store fp16. OMODE 2: final fp32 store with inverse column perm.
template <int IN, int OUT, bool RELU, bool RES, bool LN, bool SPLIT, int OMODE>
__global__ __launch_bounds__(256, 2) void gemm_f16(
    const __half* __restrict__ A, const __half* __restrict__ A2,
    const __half* __restrict__ W, const float* __restrict__ bias,
    const __half* __restrict__ res,
    const float* __restrict__ lng, const float* __restrict__ lnb,
    __half* __restrict__ Ch, float* __restrict__ Cf, int nrows)
{
    constexpr int SSTH = 80;                     // smem row stride in halves
    extern __shared__ __half smemh[];
    __half* Asm[2] = { smemh,               smemh + 128 * SSTH };
    __half* Wsm[2] = { smemh + 2 * 128 * SSTH, smemh + 3 * 128 * SSTH };
    float2* lnp    = (float2*)(smemh + 4 * 128 * SSTH);   // [2][128]

    const int tid    = threadIdx.x;
    const int lane   = tid & 31;
    const int warp   = tid >> 5;
    const int warp_m = warp & 3;
    const int warp_n = warp >> 2;
    const int g      = lane >> 2;
    const int t      = lane & 3;
    const int row0   = blockIdx.x * 128;
    const int col0   = blockIdx.y * 128;
    const int colb   = warp_n * 64;

    float acc[2][8][4];
#pragma unroll
    for (int fm = 0; fm < 2; fm++)
#pragma unroll
        for (int nf = 0; nf < 8; nf++)
#pragma unroll
            for (int r = 0; r < 4; r++) acc[fm][nf][r] = 0.f;

    constexpr int NCH = IN / 64;

    auto issue = [&](int chunk, int st) {
        const int kc = chunk * 64;               // halves
        __half* as = Asm[st];
        __half* ws = Wsm[st];
#pragma unroll
        for (int it = 0; it < 8; it++) {
            const int idx = it * 256 + tid;      // 0..2047
            const int r   = (idx >> 3) & 127;
            const int c   = idx & 7;             // 16B chunk = 8 halves
            const int kk  = kc + c * 8;
            if (idx < 1024) {
                const int grow = row0 + r;
                const bool ok  = (grow < nrows);
                const int crow = ok ? grow : 0;
                const __half* ap;
                if (SPLIT) {
                    ap = (kk < 128) ? &A[(size_t)crow * 128 + kk]
                                    : &A2[(size_t)crow * 128 + (kk - 128)];
                } else {
                    ap = &A[(size_t)crow * IN + kk];
                }
                cp16(as + r * SSTH + c * 8, ap, ok ? 16 : 0);
            } else {
                cp16(ws + r * SSTH + c * 8, &W[(size_t)(col0 + r) * IN + kk], 16);
            }
        }
        cp_commit();
    };

    auto compute = [&](int st) {
        const __half* as = Asm[st];
        const __half* ws = Wsm[st];
#pragma unroll
        for (int ks = 0; ks < 4; ks++) {
            const int kw = ks * 16 + 4 * t;      // halves offset
            unsigned a[2][4];
#pragma unroll
            for (int fm = 0; fm < 2; fm++) {
                const int rb = warp_m * 32 + fm * 16;
                const uint2 lo = *(const uint2*)(as + (rb + g) * SSTH + kw);
                const uint2 hi = *(const uint2*)(as + (rb + g + 8) * SSTH + kw);
                a[fm][0] = lo.x; a[fm][1] = hi.x;   // (r,k0k1), (r+8,k0k1)
                a[fm][2] = lo.y; a[fm][3] = hi.y;   // (r,k8k9), (r+8,k8k9)
            }
#pragma unroll
            for (int nf = 0; nf < 8; nf++) {
                const uint2 bb = *(const uint2*)(ws + (colb + nf * 8 + g) * SSTH + kw);
                mma_f16(acc[0][nf], a[0][0], a[0][1], a[0][2], a[0][3], bb.x, bb.y);
                mma_f16(acc[1][nf], a[1][0], a[1][1], a[1][2], a[1][3], bb.x, bb.y);
            }
        }
    };

    issue(0, 0);
#pragma unroll 1
    for (int ch = 0; ch < NCH; ch++) {
        if (ch + 1 < NCH) {
            issue(ch + 1, (ch + 1) & 1);
            cp_wait1();
        } else {
            cp_wait0();
        }
        __syncthreads();
        compute(ch & 1);
        __syncthreads();
    }

    // ---------------- epilogue ----------------
    float2 bias2[8];
#pragma unroll
    for (int nf = 0; nf < 8; nf++)
        bias2[nf] = *(const float2*)&bias[col0 + colb + nf * 8 + 2 * t];

#pragma unroll
    for (int fm = 0; fm < 2; fm++) {
#pragma unroll
        for (int ro = 0; ro < 2; ro++) {
            const int row  = warp_m * 32 + fm * 16 + ro * 8 + g;
            const int grow = row0 + row;
            const bool ok  = (grow < nrows);
            float s = 0.f, s2 = 0.f;
#pragma unroll
            for (int nf = 0; nf < 8; nf++) {
                float v0 = acc[fm][nf][ro * 2 + 0] + bias2[nf].x;
                float v1 = acc[fm][nf][ro * 2 + 1] + bias2[nf].y;
                if (RELU) { v0 = fmaxf(v0, 0.f); v1 = fmaxf(v1, 0.f); }
                if (RES && ok) {
                    const __half2 rh = *(const __half2*)
                        &res[(size_t)grow * OUT + col0 + colb + nf * 8 + 2 * t];
                    const float2 rv = __half22float2(rh);
                    v0 += rv.x; v1 += rv.y;
                }
                acc[fm][nf][ro * 2 + 0] = v0;
                acc[fm][nf][ro * 2 + 1] = v1;
                if (LN) { s += v0 + v1; s2 += v0 * v0 + v1 * v1; }
            }
            if (LN) {
                s  += __shfl_xor_sync(0xffffffffu, s, 1);
                s2 += __shfl_xor_sync(0xffffffffu, s2, 1);
                s  += __shfl_xor_sync(0xffffffffu, s, 2);
                s2 += __shfl_xor_sync(0xffffffffu, s2, 2);
                if (t == 0) lnp[warp_n * 128 + row] = make_float2(s, s2);
            }
        }
    }
    if (LN) __syncthreads();

#pragma unroll
    for (int fm = 0; fm < 2; fm++) {
#pragma unroll
        for (int ro = 0; ro < 2; ro++) {
            const int row  = warp_m * 32 + fm * 16 + ro * 8 + g;
            const int grow = row0 + row;
            if (grow >= nrows) continue;
            float mean = 0.f, rstd = 1.f;
            if (LN) {
                const float2 p0 = lnp[row];
                const float2 p1 = lnp[128 + row];
                const float s  = p0.x + p1.x;
                const float s2 = p0.y + p1.y;
                mean = s * (1.f / 128.f);
                const float var = s2 * (1.f / 128.f) - mean * mean;
                rstd = rsqrtf(var + 1e-5f);
            }
#pragma unroll
            for (int nf = 0; nf < 8; nf++) {
                const int col = col0 + colb + nf * 8 + 2 * t;
                float v0 = acc[fm][nf][ro * 2 + 0];
                float v1 = acc[fm][nf][ro * 2 + 1];
                if (LN) {
                    const float2 gv = *(const float2*)&lng[col];
                    const float2 bb = *(const float2*)&lnb[col];
                    v0 = (v0 - mean) * rstd * gv.x + bb.x;
                    v1 = (v1 - mean) * rstd * gv.y + bb.y;
                }
                if (OMODE == 1) {
                    *(__half2*)&Ch[(size_t)grow * OUT + col] =
                        __floats2half2_rn(v0, v1);
                } else {
                    Cf[(size_t)grow * OUT + igperm16(col)]     = v0;
                    Cf[(size_t)grow * OUT + igperm16(col + 1)] = v1;
                }
            }
        }
    }
}

// ---------------- attention: warp per node, single-pass, fp16 qkv ------------
// Scores tiny (LN'd inputs x 0.02 weights) -> exp without max-shift is safe.
__global__ __launch_bounds__(256) void attn_kernel(
    const __half* __restrict__ qkv, const int* __restrict__ samp,
    __half* __restrict__ out, int n)
{
    const int warp = (blockIdx.x * blockDim.x + threadIdx.x) >> 5;
    const int lane = threadIdx.x & 31;
    if (warp >= n) return;
    const int node = warp;
    const int c0 = lane * 4;
    const float scale = 0.17677669529663687f;   // 1/sqrt(32)

    const uint2 qraw = *(const uint2*)&qkv[(size_t)node * 384 + c0];
    const float2 q01 = __half22float2(*reinterpret_cast<const __half2*>(&qraw.x));
    const float2 q23 = __half22float2(*reinterpret_cast<const __half2*>(&qraw.y));
    float sum = 0.f;
    float4 acc = make_float4(0.f, 0.f, 0.f, 0.f);

#pragma unroll
    for (int j0 = 0; j0 < KATT; j0 += 4) {
        int id[4];
#pragma unroll
        for (int jj = 0; jj < 4; jj++)
            id[jj] = __ldg(&samp[node * KATT + j0 + jj]);
        uint2 kraw[4], vraw[4];
#pragma unroll
        for (int jj = 0; jj < 4; jj++) {
            const size_t base = (size_t)id[jj] * 384 + c0;
            kraw[jj] = *(const uint2*)&qkv[base + 128];
            vraw[jj] = *(const uint2*)&qkv[base + 256];
        }
#pragma unroll
        for (int jj = 0; jj < 4; jj++) {
            const float2 k01 = __half22float2(
                *reinterpret_cast<const __half2*>(&kraw[jj].x));
            const float2 k23 = __half22float2(
                *reinterpret_cast<const __half2*>(&kraw[jj].y));
            float d = q01.x * k01.x + q01.y * k01.y + q23.x * k23.x + q23.y * k23.y;
            d += __shfl_xor_sync(0xffffffffu, d, 1);
            d += __shfl_xor_sync(0xffffffffu, d, 2);
            d += __shfl_xor_sync(0xffffffffu, d, 4);
            const float e = __expf(d * scale);
            sum += e;
            const float2 v01 = __half22float2(
                *reinterpret_cast<const __half2*>(&vraw[jj].x));
            const float2 v23 = __half22float2(
                *reinterpret_cast<const __half2*>(&vraw[jj].y));
            acc.x += e * v01.x; acc.y += e * v01.y;
            acc.z += e * v23.x; acc.w += e * v23.y;
        }
    }
    const float inv = 1.f / sum;
    uint2 o;
    *reinterpret_cast<__half2*>(&o.x) = __floats2half2_rn(acc.x * inv, acc.y * inv);
    *reinterpret_cast<__half2*>(&o.y) = __floats2half2_rn(acc.z * inv, acc.w * inv);
    *(uint2*)&out[(size_t)node * 128 + c0] = o;
}

// ---------------- GNN CSR build + aggregate ----------------
__global__ void zero_kernel(int* __restrict__ a, int* __restrict__ b, int n) {
    const int i = blockIdx.x * blockDim.x + threadIdx.x;
    if (i < n) { a[i] = 0; b[i] = 0; }
}

__global__ void hist_kernel(const int* __restrict__ src, int* __restrict__ deg, int e) {
    const int i = blockIdx.x * blockDim.x + threadIdx.x;
    if (i < e) atomicAdd(&deg[src[i]], 1);
}

__global__ __launch_bounds__(256) void scan1_kernel(
    const int* __restrict__ deg, int* __restrict__ off, int* __restrict__ bsum, int n)
{
    __shared__ int wsum[8];
    const int tid  = threadIdx.x;
    const int lane = tid & 31, wid = tid >> 5;
    const int base = blockIdx.x * SCAN_TILE + tid * 16;

    int v[16];
    int tsum = 0;
#pragma unroll
    for (int i = 0; i < 16; i++) {
        const int gi = base + i;
        v[i] = (gi < n) ? deg[gi] : 0;
        tsum += v[i];
    }
    int x = tsum;
#pragma unroll
    for (int d = 1; d < 32; d <<= 1) {
        const int t = __shfl_up_sync(0xffffffffu, x, d);
        if (lane >= d) x += t;
    }
    if (lane == 31) wsum[wid] = x;
    __syncthreads();
    int wpre = 0;
#pragma unroll
    for (int w = 0; w < 8; w++) wpre += (w < wid) ? wsum[w] : 0;
    int run = wpre + x - tsum;
#pragma unroll
    for (int i = 0; i < 16; i++) {
        const int gi = base + i;
        if (gi < n) off[gi] = run;
        run += v[i];
    }
    if (tid == 255) bsum[blockIdx.x] = wpre + x;
}

__global__ __launch_bounds__(256) void scan2_kernel(
    const int* __restrict__ bsum, int* __restrict__ off, int n)
{
    __shared__ int pre_s, tot_s;
    if (threadIdx.x == 0) {
        int p = 0, t = 0;
#pragma unroll
        for (int b = 0; b < SCAN_BLOCKS; b++) {
            if (b < (int)blockIdx.x) p += bsum[b];
            t += bsum[b];
        }
        pre_s = p; tot_s = t;
    }
    __syncthreads();
    const int pre = pre_s;
    const int base = blockIdx.x * SCAN_TILE + threadIdx.x * 16;
#pragma unroll
    for (int i = 0; i < 16; i++) {
        const int gi = base + i;
        if (gi < n) off[gi] += pre;
    }
    if (blockIdx.x == 0 && threadIdx.x == 0) off[n] = tot_s;
}

__global__ void scatter_kernel(const int* __restrict__ src, const int* __restrict__ dst,
                               const int* __restrict__ off, int* __restrict__ cnt,
                               int* __restrict__ csr, int e) {
    const int i = blockIdx.x * blockDim.x + threadIdx.x;
    if (i < e) {
        const int s = src[i];
        const int pos = off[s] + atomicAdd(&cnt[s], 1);
        csr[pos] = dst[i];
    }
}

// warp per node: neigh[n] = sum over edges of h[dst] (fp16 rows, 256 B)
__global__ __launch_bounds__(256) void agg_kernel(
    const __half* __restrict__ h, const int* __restrict__ off,
    const int* __restrict__ csr, __half* __restrict__ neigh, int n)
{
    const int warp = (blockIdx.x * blockDim.x + threadIdx.x) >> 5;
    const int lane = threadIdx.x & 31;
    if (warp >= n) return;
    const int beg = off[warp], end = off[warp + 1];
    const int c0 = lane * 4;
    float4 acc0 = make_float4(0.f, 0.f, 0.f, 0.f);
    float4 acc1 = make_float4(0.f, 0.f, 0.f, 0.f);
    float4 acc2 = make_float4(0.f, 0.f, 0.f, 0.f);
    float4 acc3 = make_float4(0.f, 0.f, 0.f, 0.f);
    int e = beg;
    for (; e + 4 <= end; e += 4) {
        const int d0 = csr[e];
        const int d1 = csr[e + 1];
        const int d2 = csr[e + 2];
        const int d3 = csr[e + 3];
        const uint2 r0 = *(const uint2*)&h[(size_t)d0 * 128 + c0];
        const uint2 r1 = *(const uint2*)&h[(size_t)d1 * 128 + c0];
        const uint2 r2 = *(const uint2*)&h[(size_t)d2 * 128 + c0];
        const uint2 r3 = *(const uint2*)&h[(size_t)d3 * 128 + c0];
        {
            const float2 a = __half22float2(*reinterpret_cast<const __half2*>(&r0.x));
            const float2 b = __half22float2(*reinterpret_cast<const __half2*>(&r0.y));
            acc0.x += a.x; acc0.y += a.y; acc0.z += b.x; acc0.w += b.y;
        }
        {
            const float2 a = __half22float2(*reinterpret_cast<const __half2*>(&r1.x));
            const float2 b = __half22float2(*reinterpret_cast<const __half2*>(&r1.y));
            acc1.x += a.x; acc1.y += a.y; acc1.z += b.x; acc1.w += b.y;
        }
        {
            const float2 a = __half22float2(*reinterpret_cast<const __half2*>(&r2.x));
            const float2 b = __half22float2(*reinterpret_cast<const __half2*>(&r2.y));
            acc2.x += a.x; acc2.y += a.y; acc2.z += b.x; acc2.w += b.y;
        }
        {
            const float2 a = __half22float2(*reinterpret_cast<const __half2*>(&r3.x));
            const float2 b = __half22float2(*reinterpret_cast<const __half2*>(&r3.y));
            acc3.x += a.x; acc3.y += a.y; acc3.z += b.x; acc3.w += b.y;
        }
    }
    for (; e < end; e++) {
        const int d0 = csr[e];
        const uint2 r0 = *(const uint2*)&h[(size_t)d0 * 128 + c0];
        const float2 a = __half22float2(*reinterpret_cast<const __half2*>(&r0.x));
        const float2 b = __half22float2(*reinterpret_cast<const __half2*>(&r0.y));
        acc0.x += a.x; acc0.y += a.y; acc0.z += b.x; acc0.w += b.y;
    }
    acc0.x += acc1.x; acc0.y += acc1.y; acc0.z += acc1.z; acc0.w += acc1.w;
    acc2.x += acc3.x; acc2.y += acc3.y; acc2.z += acc3.z; acc2.w += acc3.w;
    acc0.x += acc2.x; acc0.y += acc2.y; acc0.z += acc2.z; acc0.w += acc2.w;
    uint2 o;
    *reinterpret_cast<__half2*>(&o.x) = __floats2half2_rn(acc0.x, acc0.y);
    *reinterpret_cast<__half2*>(&o.y) = __floats2half2_rn(acc0.z, acc0.w);
    *(uint2*)&neigh[(size_t)warp * 128 + c0] = o;
}

// ---------------- host orchestration ----------------
extern "C" void kernel_launch(void* const* d_in, const int* in_sizes, int n_in,
                              void* d_out, int out_size)
{
    const float* x       = (const float*)d_in[0];
    const int*   samples = (const int*)d_in[1];
    const int*   esrc    = (const int*)d_in[2];
    const int*   edst    = (const int*)d_in[3];
    const float* t_in_w  = (const float*)d_in[4];
    const float* t_in_b  = (const float*)d_in[5];
    const float* t_out_w = (const float*)d_in[6];
    const float* t_out_b = (const float*)d_in[7];
    const float* t_f_w1  = (const float*)d_in[8];
    const float* t_f_b1  = (const float*)d_in[9];
    const float* t_f_w2  = (const float*)d_in[10];
    const float* t_f_b2  = (const float*)d_in[11];
    const float* ln1g    = (const float*)d_in[12];
    const float* ln1b    = (const float*)d_in[13];
    const float* ln2g    = (const float*)d_in[14];
    const float* ln2b    = (const float*)d_in[15];
    const float* gw      = (const float*)d_in[16];
    const float* gb      = (const float*)d_in[17];
    const float* glng    = (const float*)d_in[18];
    const float* glnb    = (const float*)d_in[19];

    __half *pqkv, *pattn, *pa, *ptmp, *ph, *ph2, *pneigh, *phx;
    int *pdeg, *poff, *pcnt, *pcsr, *pbsum;
    __half *wqkv, *wout, *wf1, *wf2, *wg;
    float *bqkv, *bout, *bf1, *bf2, *l1g, *l1b, *l2g, *l2b, *bg, *gg, *gbv;
    cudaGetSymbolAddress((void**)&pqkv,   g_qkv);
    cudaGetSymbolAddress((void**)&pattn,  g_attn);
    cudaGetSymbolAddress((void**)&pa,     g_a);
    cudaGetSymbolAddress((void**)&ptmp,   g_tmp);
    cudaGetSymbolAddress((void**)&ph,     g_h);
    cudaGetSymbolAddress((void**)&ph2,    g_h2);
    cudaGetSymbolAddress((void**)&pneigh, g_neigh);
    cudaGetSymbolAddress((void**)&phx,    g_hx);
    cudaGetSymbolAddress((void**)&pdeg,   g_deg);
    cudaGetSymbolAddress((void**)&poff,   g_off);
    cudaGetSymbolAddress((void**)&pcnt,   g_cnt);
    cudaGetSymbolAddress((void**)&pcsr,   g_csr);
    cudaGetSymbolAddress((void**)&pbsum,  g_bsum);
    cudaGetSymbolAddress((void**)&wqkv,   g_wqkv);
    cudaGetSymbolAddress((void**)&wout,   g_wout);
    cudaGetSymbolAddress((void**)&wf1,    g_wf1);
    cudaGetSymbolAddress((void**)&wf2,    g_wf2);
    cudaGetSymbolAddress((void**)&wg,     g_wg);
    cudaGetSymbolAddress((void**)&bqkv,   g_bqkv);
    cudaGetSymbolAddress((void**)&bout,   g_bout);
    cudaGetSymbolAddress((void**)&bf1,    g_bf1);
    cudaGetSymbolAddress((void**)&bf2,    g_bf2);
    cudaGetSymbolAddress((void**)&l1g,    g_l1g);
    cudaGetSymbolAddress((void**)&l1b,    g_l1b);
    cudaGetSymbolAddress((void**)&l2g,    g_l2g);
    cudaGetSymbolAddress((void**)&l2b,    g_l2b);
    cudaGetSymbolAddress((void**)&bg,     g_bg);
    cudaGetSymbolAddress((void**)&gg,     g_gg);
    cudaGetSymbolAddress((void**)&gbv,    g_gb);

    const int n = NN;
    const int e = EE;
    const int GX = (n + 127) / 128;
    const int WARP_GRID = (n + 7) / 8;
    const int EG = (e + 255) / 256;
    const size_t SMEMSZ = (size_t)4 * 128 * 80 * sizeof(__half) + 256 * sizeof(float2);

    cudaFuncSetAttribute(gemm_f16<128, 384, false, false, false, false, 1>,
                         cudaFuncAttributeMaxDynamicSharedMemorySize, (int)SMEMSZ);
    cudaFuncSetAttribute(gemm_f16<128, 128, false, true, true, false, 1>,
                         cudaFuncAttributeMaxDynamicSharedMemorySize, (int)SMEMSZ);
    cudaFuncSetAttribute(gemm_f16<128, 512, true, false, false, false, 1>,
                         cudaFuncAttributeMaxDynamicSharedMemorySize, (int)SMEMSZ);
    cudaFuncSetAttribute(gemm_f16<512, 128, false, true, true, false, 1>,
                         cudaFuncAttributeMaxDynamicSharedMemorySize, (int)SMEMSZ);
    cudaFuncSetAttribute(gemm_f16<512, 128, false, true, true, false, 2>,
                         cudaFuncAttributeMaxDynamicSharedMemorySize, (int)SMEMSZ);
    cudaFuncSetAttribute(gemm_f16<256, 128, true, true, true, true, 1>,
                         cudaFuncAttributeMaxDynamicSharedMemorySize, (int)SMEMSZ);

    // side stream + events (created once; graph fork/join pattern)
    static cudaStream_t sB = nullptr;
    static cudaEvent_t evFork = nullptr, evJoin = nullptr;
    if (sB == nullptr) {
        cudaStreamCreateWithFlags(&sB, cudaStreamNonBlocking);
        cudaEventCreateWithFlags(&evFork, cudaEventDisableTiming);
        cudaEventCreateWithFlags(&evJoin, cudaEventDisableTiming);
    }

    // ---- parameter conversion tables ----
    PTab tabA; int na = 0;
    tabA.e[na++] = { t_in_w,  wqkv, 384, 128, 0 };
    tabA.e[na++] = { t_out_w, wout, 128, 128, 0 };
    tabA.e[na++] = { t_f_w1,  wf1,  512, 128, 0 };
    tabA.e[na++] = { t_f_w2,  wf2,  128, 512, 0 };
    tabA.e[na++] = { t_in_b,  bqkv, 1, 384, 1 };
    tabA.e[na++] = { t_out_b, bout, 1, 128, 1 };
    tabA.e[na++] = { t_f_b1,  bf1,  1, 512, 1 };
    tabA.e[na++] = { t_f_b2,  bf2,  1, 128, 1 };
    tabA.e[na++] = { ln1g, l1g, 1, 128, 1 };
    tabA.e[na++] = { ln1b, l1b, 1, 128, 1 };
    tabA.e[na++] = { ln2g, l2g, 1, 128, 1 };
    tabA.e[na++] = { ln2b, l2b, 1, 128, 1 };
    PTab tabB; int nb = 0;
    for (int i = 1; i < 3; i++) {
        tabB.e[nb++] = { t_in_w  + (size_t)i * 384 * 128, wqkv + (size_t)i * 384 * 128, 384, 128, 0 };
        tabB.e[nb++] = { t_out_w + (size_t)i * 128 * 128, wout + (size_t)i * 128 * 128, 128, 128, 0 };
        tabB.e[nb++] = { t_f_w1  + (size_t)i * 512 * 128, wf1  + (size_t)i * 512 * 128, 512, 128, 0 };
        tabB.e[nb++] = { t_f_w2  + (size_t)i * 128 * 512, wf2  + (size_t)i * 128 * 512, 128, 512, 0 };
        tabB.e[nb++] = { t_in_b  + i * 384, bqkv + i * 384, 1, 384, 1 };
        tabB.e[nb++] = { t_out_b + i * 128, bout + i * 128, 1, 128, 1 };
        tabB.e[nb++] = { t_f_b1  + i * 512, bf1  + i * 512, 1, 512, 1 };
        tabB.e[nb++] = { t_f_b2  + i * 128, bf2  + i * 128, 1, 128, 1 };
        tabB.e[nb++] = { ln1g + i * 128, l1g + i * 128, 1, 128, 1 };
        tabB.e[nb++] = { ln1b + i * 128, l1b + i * 128, 1, 128, 1 };
        tabB.e[nb++] = { ln2g + i * 128, l2g + i * 128, 1, 128, 1 };
        tabB.e[nb++] = { ln2b + i * 128, l2b + i * 128, 1, 128, 1 };
    }
    for (int i = 0; i < 2; i++) {
        tabB.e[nb++] = { gw + (size_t)i * 128 * 256, wg + (size_t)i * 128 * 256, 128, 256, 0 };
        tabB.e[nb++] = { gb   + i * 128, bg  + i * 128, 1, 128, 1 };
        tabB.e[nb++] = { glng + i * 128, gg  + i * 128, 1, 128, 1 };
        tabB.e[nb++] = { glnb + i * 128, gbv + i * 128, 1, 128, 1 };
    }

    // fork point: side work depends only on inputs
    cudaEventRecord(evFork, 0);
    cudaStreamWaitEvent(sB, evFork, 0);

    // ---- main stream: critical conversions + trans1 ----
    param_conv<<<dim3(64, na), 256>>>(tabA, na);
    conv_x<<<(NN * 128 + 255) / 256, 256>>>(x, phx);

    // ---- side stream: rest of params + CSR build (overlaps trans1) ----
    param_conv<<<dim3(64, nb), 256, 0, sB>>>(tabB, nb);
    zero_kernel<<<(n + 255) / 256, 256, 0, sB>>>(pdeg, pcnt, n);
    hist_kernel<<<EG, 256, 0, sB>>>(esrc, pdeg, e);
    scan1_kernel<<<SCAN_BLOCKS, 256, 0, sB>>>(pdeg, poff, pbsum, n);
    scan2_kernel<<<SCAN_BLOCKS, 256, 0, sB>>>(pbsum, poff, n);
    scatter_kernel<<<EG, 256, 0, sB>>>(esrc, edst, poff, pcnt, pcsr, e);
    cudaEventRecord(evJoin, sB);

    // ---- transformer layer ----
    auto run_trans = [&](const __half* hin, __half* hout, int i, bool final_layer) {
        gemm_f16<128, 384, false, false, false, false, 1><<<dim3(GX, 3), 256, SMEMSZ>>>(
            hin, nullptr, wqkv + (size_t)i * 384 * 128, bqkv + i * 384,
            nullptr, nullptr, nullptr, pqkv, nullptr, n);
        attn_kernel<<<WARP_GRID, 256>>>(pqkv, samples, pattn, n);
        gemm_f16<128, 128, false, true, true, false, 1><<<dim3(GX, 1), 256, SMEMSZ>>>(
            pattn, nullptr, wout + (size_t)i * 128 * 128, bout + i * 128,
            hin, l1g + i * 128, l1b + i * 128, pa, nullptr, n);
        gemm_f16<128, 512, true, false, false, false, 1><<<dim3(GX, 4), 256, SMEMSZ>>>(
            pa, nullptr, wf1 + (size_t)i * 512 * 128, bf1 + i * 512,
            nullptr, nullptr, nullptr, ptmp, nullptr, n);
        if (final_layer) {
            gemm_f16<512, 128, false, true, true, false, 2><<<dim3(GX, 1), 256, SMEMSZ>>>(
                ptmp, nullptr, wf2 + (size_t)i * 128 * 512, bf2 + i * 128,
                pa, l2g + i * 128, l2b + i * 128, nullptr, (float*)d_out, n);
        } else {
            gemm_f16<512, 128, false, true, true, false, 1><<<dim3(GX, 1), 256, SMEMSZ>>>(
                ptmp, nullptr, wf2 + (size_t)i * 128 * 512, bf2 + i * 128,
                pa, l2g + i * 128, l2b + i * 128, hout, nullptr, n);
        }
    };

    auto run_gnn = [&](const __half* hin, __half* hout, int i) {
        agg_kernel<<<WARP_GRID, 256>>>(hin, poff, pcsr, pneigh, n);
        gemm_f16<256, 128, true, true, true, true, 1><<<dim3(GX, 1), 256, SMEMSZ>>>(
            hin, pneigh, wg + (size_t)i * 128 * 256, bg + i * 128,
            hin, gg + i * 128, gbv + i * 128, hout, nullptr, n);
    };

    run_trans(phx, ph, 0, false);

    // join before first aggregation
    cudaStreamWaitEvent(0, evJoin, 0);

    run_gnn(ph, ph2, 0);
    run_trans(ph2, ph, 1, false);
    run_gnn(ph, ph2, 1);
    run_trans(ph2, nullptr, 2, true);
}

// round 12
// speedup vs baseline: 1.0057x; 1.0057x over previous
#include <cuda_runtime.h>
#include <cuda_fp16.h>

#define NN 50000
#define DD 128
#define EE 1600000
#define KATT 20
#define SCAN_TILE 4096
#define SCAN_BLOCKS ((NN + SCAN_TILE - 1) / SCAN_TILE)

// ---------------- scratch (static device allocations) ----------------
__device__ __half g_qkv[NN * 384];
__device__ __half g_attn[NN * DD];
__device__ __half g_a[NN * DD];
__device__ __half g_tmp[NN * 512];
__device__ __half g_h[NN * DD];
__device__ __half g_h2[NN * DD];
__device__ __half g_neigh[NN * DD];
__device__ __half g_hx[NN * DD];
__device__ int   g_deg[NN];
__device__ int   g_off[NN + 1];
__device__ int   g_cnt[NN];
__device__ int   g_csr[EE];
__device__ int   g_bsum[SCAN_BLOCKS];

// converted (fp16, pair-permuted) weights; fp32 permuted biases/LN params
__device__ __half g_wqkv[3 * 384 * 128];
__device__ __half g_wout[3 * 128 * 128];
__device__ __half g_wf1 [3 * 512 * 128];
__device__ __half g_wf2 [3 * 128 * 512];
__device__ __half g_wg  [2 * 128 * 256];
__device__ float g_bqkv[3 * 384];
__device__ float g_bout[3 * 128];
__device__ float g_bf1 [3 * 512];
__device__ float g_bf2 [3 * 128];
__device__ float g_l1g [3 * 128];
__device__ float g_l1b [3 * 128];
__device__ float g_l2g [3 * 128];
__device__ float g_l2b [3 * 128];
__device__ float g_bg  [2 * 128];
__device__ float g_gg  [2 * 128];
__device__ float g_gb  [2 * 128];

// ---------------- helpers ----------------
// within-16 column PAIR permutation (logical -> physical):
// pair p (cols 2p,2p+1) -> np = ((p&3)<<1)|(p>>2). Keeps pairs adjacent so
// thread t's mma k-halves {2t,2t+1} and {2t+8,2t+9} form one 8B word.
__device__ __forceinline__ int gperm16(int i) {
    const int p  = (i >> 1) & 7;
    const int o  = i & 1;
    const int np = ((p & 3) << 1) | (p >> 2);
    return (i & ~15) | (np << 1) | o;
}
// inverse (physical -> logical)
__device__ __forceinline__ int igperm16(int c) {
    const int np = (c >> 1) & 7;
    const int o  = c & 1;
    const int p  = ((np >> 1) & 3) | ((np & 1) << 2);
    return (c & ~15) | (p << 1) | o;
}

__device__ __forceinline__ void mma_f16(float c[4], unsigned a0, unsigned a1,
                                        unsigned a2, unsigned a3,
                                        unsigned b0, unsigned b1) {
    asm("mma.sync.aligned.m16n8k16.row.col.f32.f16.f16.f32 "
        "{%0,%1,%2,%3}, {%4,%5,%6,%7}, {%8,%9}, {%0,%1,%2,%3};\n"
        : "+f"(c[0]), "+f"(c[1]), "+f"(c[2]), "+f"(c[3])
        : "r"(a0), "r"(a1), "r"(a2), "r"(a3), "r"(b0), "r"(b1));
}

__device__ __forceinline__ void cp16(void* sdst, const void* gsrc, int sz) {
    unsigned s = (unsigned)__cvta_generic_to_shared(sdst);
    asm volatile("cp.async.cg.shared.global [%0], [%1], 16, %2;\n"
                 :: "r"(s), "l"(gsrc), "r"(sz));
}
__device__ __forceinline__ void cp_commit() {
    asm volatile("cp.async.commit_group;\n");
}
__device__ __forceinline__ void cp_wait1() {
    asm volatile("cp.async.wait_group 1;\n");
}
__device__ __forceinline__ void cp_wait0() {
    asm volatile("cp.async.wait_group 0;\n");
}

// ---------------- parameter conversion ----------------
struct PEnt { const float* s; void* d; int rows; int cols; int mode; };
struct PTab { PEnt e[32]; };

__global__ void param_conv(PTab t, int n) {
    const int ei = blockIdx.y;
    if (ei >= n) return;
    const PEnt en = t.e[ei];
    const int total = en.rows * en.cols;
    for (int i = blockIdx.x * blockDim.x + threadIdx.x; i < total;
         i += gridDim.x * blockDim.x) {
        if (en.mode == 0) {           // matrix: permute both dims, fp16
            const int r = i / en.cols, c = i % en.cols;
            ((__half*)en.d)[(size_t)gperm16(r) * en.cols + gperm16(c)] =
                __float2half_rn(en.s[i]);
        } else {                      // vector: permute only, fp32
            ((float*)en.d)[gperm16(i)] = en.s[i];
        }
    }
}

__global__ void conv_x(const float* __restrict__ x, __half* __restrict__ o) {
    const int i = blockIdx.x * blockDim.x + threadIdx.x;
    if (i < NN * 128) {
        const int r = i >> 7, c = i & 127;
        o[(r << 7) + gperm16(c)] = __float2half_rn(x[i]);
    }
}

// ---------------- fused FP16 tensor-core GEMM (cp.async pipelined) ----------------
// All operands fp16 in permuted world. Block 128x128, 8 warps (4m x 2n),
// warp tile 32x64, BK=64 halves, 2-stage cp.async. Smem row stride 160B
// (conflict-free 8B fragment loads). Accum fp32, epilogue fp32.
// OMODE 1: store fp16. OMODE 2: final fp32 store with inverse column perm.
template <int IN, int OUT, bool RELU, bool RES, bool LN, bool SPLIT, int OMODE>
__global__ __launch_bounds__(256, 2) void gemm_f16(
    const __half* __restrict__ A, const __half* __restrict__ A2,
    const __half* __restrict__ W, const float* __restrict__ bias,
    const __half* __restrict__ res,
    const float* __restrict__ lng, const float* __restrict__ lnb,
    __half* __restrict__ Ch, float* __restrict__ Cf, int nrows)
{
    constexpr int SSTH = 80;                     // smem row stride in halves
    extern __shared__ __half smemh[];
    __half* Asm[2] = { smemh,               smemh + 128 * SSTH };
    __half* Wsm[2] = { smemh + 2 * 128 * SSTH, smemh + 3 * 128 * SSTH };
    float2* lnp    = (float2*)(smemh + 4 * 128 * SSTH);   // [2][128]

    const int tid    = threadIdx.x;
    const int lane   = tid & 31;
    const int warp   = tid >> 5;
    const int warp_m = warp & 3;
    const int warp_n = warp >> 2;
    const int g      = lane >> 2;
    const int t      = lane & 3;
    const int row0   = blockIdx.x * 128;
    const int col0   = blockIdx.y * 128;
    const int colb   = warp_n * 64;

    float acc[2][8][4];
#pragma unroll
    for (int fm = 0; fm < 2; fm++)
#pragma unroll
        for (int nf = 0; nf < 8; nf++)
#pragma unroll
            for (int r = 0; r < 4; r++) acc[fm][nf][r] = 0.f;

    constexpr int NCH = IN / 64;

    auto issue = [&](int chunk, int st) {
        const int kc = chunk * 64;               // halves
        __half* as = Asm[st];
        __half* ws = Wsm[st];
#pragma unroll
        for (int it = 0; it < 8; it++) {
            const int idx = it * 256 + tid;      // 0..2047
            const int r   = (idx >> 3) & 127;
            const int c   = idx & 7;             // 16B chunk = 8 halves
            const int kk  = kc + c * 8;
            if (idx < 1024) {
                const int grow = row0 + r;
                const bool ok  = (grow < nrows);
                const int crow = ok ? grow : 0;
                const __half* ap;
                if (SPLIT) {
                    ap = (kk < 128) ? &A[(size_t)crow * 128 + kk]
                                    : &A2[(size_t)crow * 128 + (kk - 128)];
                } else {
                    ap = &A[(size_t)crow * IN + kk];
                }
                cp16(as + r * SSTH + c * 8, ap, ok ? 16 : 0);
            } else {
                cp16(ws + r * SSTH + c * 8, &W[(size_t)(col0 + r) * IN + kk], 16);
            }
        }
        cp_commit();
    };

    auto compute = [&](int st) {
        const __half* as = Asm[st];
        const __half* ws = Wsm[st];
#pragma unroll
        for (int ks = 0; ks < 4; ks++) {
            const int kw = ks * 16 + 4 * t;      // halves offset
            unsigned a[2][4];
#pragma unroll
            for (int fm = 0; fm < 2; fm++) {
                const int rb = warp_m * 32 + fm * 16;
                const uint2 lo = *(const uint2*)(as + (rb + g) * SSTH + kw);
                const uint2 hi = *(const uint2*)(as + (rb + g + 8) * SSTH + kw);
                a[fm][0] = lo.x; a[fm][1] = hi.x;   // (r,k0k1), (r+8,k0k1)
                a[fm][2] = lo.y; a[fm][3] = hi.y;   // (r,k8k9), (r+8,k8k9)
            }
#pragma unroll
            for (int nf = 0; nf < 8; nf++) {
                const uint2 bb = *(const uint2*)(ws + (colb + nf * 8 + g) * SSTH + kw);
                mma_f16(acc[0][nf], a[0][0], a[0][1], a[0][2], a[0][3], bb.x, bb.y);
                mma_f16(acc[1][nf], a[1][0], a[1][1], a[1][2], a[1][3], bb.x, bb.y);
            }
        }
    };

    issue(0, 0);
#pragma unroll 1
    for (int ch = 0; ch < NCH; ch++) {
        if (ch + 1 < NCH) {
            issue(ch + 1, (ch + 1) & 1);
            cp_wait1();
        } else {
            cp_wait0();
        }
        __syncthreads();
        compute(ch & 1);
        __syncthreads();
    }

    // ---------------- epilogue ----------------
    float2 bias2[8];
#pragma unroll
    for (int nf = 0; nf < 8; nf++)
        bias2[nf] = *(const float2*)&bias[col0 + colb + nf * 8 + 2 * t];

#pragma unroll
    for (int fm = 0; fm < 2; fm++) {
#pragma unroll
        for (int ro = 0; ro < 2; ro++) {
            const int row  = warp_m * 32 + fm * 16 + ro * 8 + g;
            const int grow = row0 + row;
            const bool ok  = (grow < nrows);
            float s = 0.f, s2 = 0.f;
#pragma unroll
            for (int nf = 0; nf < 8; nf++) {
                float v0 = acc[fm][nf][ro * 2 + 0] + bias2[nf].x;
                float v1 = acc[fm][nf][ro * 2 + 1] + bias2[nf].y;
                if (RELU) { v0 = fmaxf(v0, 0.f); v1 = fmaxf(v1, 0.f); }
                if (RES && ok) {
                    const __half2 rh = *(const __half2*)
                        &res[(size_t)grow * OUT + col0 + colb + nf * 8 + 2 * t];
                    const float2 rv = __half22float2(rh);
                    v0 += rv.x; v1 += rv.y;
                }
                acc[fm][nf][ro * 2 + 0] = v0;
                acc[fm][nf][ro * 2 + 1] = v1;
                if (LN) { s += v0 + v1; s2 += v0 * v0 + v1 * v1; }
            }
            if (LN) {
                s  += __shfl_xor_sync(0xffffffffu, s, 1);
                s2 += __shfl_xor_sync(0xffffffffu, s2, 1);
                s  += __shfl_xor_sync(0xffffffffu, s, 2);
                s2 += __shfl_xor_sync(0xffffffffu, s2, 2);
                if (t == 0) lnp[warp_n * 128 + row] = make_float2(s, s2);
            }
        }
    }
    if (LN) __syncthreads();

#pragma unroll
    for (int fm = 0; fm < 2; fm++) {
#pragma unroll
        for (int ro = 0; ro < 2; ro++) {
            const int row  = warp_m * 32 + fm * 16 + ro * 8 + g;
            const int grow = row0 + row;
            if (grow >= nrows) continue;
            float mean = 0.f, rstd = 1.f;
            if (LN) {
                const float2 p0 = lnp[row];
                const float2 p1 = lnp[128 + row];
                const float s  = p0.x + p1.x;
                const float s2 = p0.y + p1.y;
                mean = s * (1.f / 128.f);
                const float var = s2 * (1.f / 128.f) - mean * mean;
                rstd = rsqrtf(var + 1e-5f);
            }
#pragma unroll
            for (int nf = 0; nf < 8; nf++) {
                const int col = col0 + colb + nf * 8 + 2 * t;
                float v0 = acc[fm][nf][ro * 2 + 0];
                float v1 = acc[fm][nf][ro * 2 + 1];
                if (LN) {
                    const float2 gv = *(const float2*)&lng[col];
                    const float2 bb = *(const float2*)&lnb[col];
                    v0 = (v0 - mean) * rstd * gv.x + bb.x;
                    v1 = (v1 - mean) * rstd * gv.y + bb.y;
                }
                if (OMODE == 1) {
                    *(__half2*)&Ch[(size_t)grow * OUT + col] =
                        __floats2half2_rn(v0, v1);
                } else {
                    Cf[(size_t)grow * OUT + igperm16(col)]     = v0;
                    Cf[(size_t)grow * OUT + igperm16(col + 1)] = v1;
                }
            }
        }
    }
}

// ---------------- attention: warp per node, single-pass, fp16 qkv ------------
// Scores tiny (LN'd inputs x 0.02 weights) -> exp without max-shift is safe.
__global__ __launch_bounds__(256) void attn_kernel(
    const __half* __restrict__ qkv, const int* __restrict__ samp,
    __half* __restrict__ out, int n)
{
    const int warp = (blockIdx.x * blockDim.x + threadIdx.x) >> 5;
    const int lane = threadIdx.x & 31;
    if (warp >= n) return;
    const int node = warp;
    const int c0 = lane * 4;
    const float scale = 0.17677669529663687f;   // 1/sqrt(32)

    const uint2 qraw = *(const uint2*)&qkv[(size_t)node * 384 + c0];
    const float2 q01 = __half22float2(*reinterpret_cast<const __half2*>(&qraw.x));
    const float2 q23 = __half22float2(*reinterpret_cast<const __half2*>(&qraw.y));
    float sum = 0.f;
    float4 acc = make_float4(0.f, 0.f, 0.f, 0.f);

#pragma unroll
    for (int j0 = 0; j0 < KATT; j0 += 4) {
        int id[4];
#pragma unroll
        for (int jj = 0; jj < 4; jj++)
            id[jj] = __ldg(&samp[node * KATT + j0 + jj]);
        uint2 kraw[4], vraw[4];
#pragma unroll
        for (int jj = 0; jj < 4; jj++) {
            const size_t base = (size_t)id[jj] * 384 + c0;
            kraw[jj] = *(const uint2*)&qkv[base + 128];
            vraw[jj] = *(const uint2*)&qkv[base + 256];
        }
#pragma unroll
        for (int jj = 0; jj < 4; jj++) {
            const float2 k01 = __half22float2(
                *reinterpret_cast<const __half2*>(&kraw[jj].x));
            const float2 k23 = __half22float2(
                *reinterpret_cast<const __half2*>(&kraw[jj].y));
            float d = q01.x * k01.x + q01.y * k01.y + q23.x * k23.x + q23.y * k23.y;
            d += __shfl_xor_sync(0xffffffffu, d, 1);
            d += __shfl_xor_sync(0xffffffffu, d, 2);
            d += __shfl_xor_sync(0xffffffffu, d, 4);
            const float e = __expf(d * scale);
            sum += e;
            const float2 v01 = __half22float2(
                *reinterpret_cast<const __half2*>(&vraw[jj].x));
            const float2 v23 = __half22float2(
                *reinterpret_cast<const __half2*>(&vraw[jj].y));
            acc.x += e * v01.x; acc.y += e * v01.y;
            acc.z += e * v23.x; acc.w += e * v23.y;
        }
    }
    const float inv = 1.f / sum;
    uint2 o;
    *reinterpret_cast<__half2*>(&o.x) = __floats2half2_rn(acc.x * inv, acc.y * inv);
    *reinterpret_cast<__half2*>(&o.y) = __floats2half2_rn(acc.z * inv, acc.w * inv);
    *(uint2*)&out[(size_t)node * 128 + c0] = o;
}

// ---------------- GNN CSR build + aggregate ----------------
__global__ void zero_kernel(int* __restrict__ a, int* __restrict__ b, int n) {
    const int i = blockIdx.x * blockDim.x + threadIdx.x;
    if (i < n) { a[i] = 0; b[i] = 0; }
}

__global__ void hist_kernel(const int* __restrict__ src, int* __restrict__ deg, int e) {
    const int i = blockIdx.x * blockDim.x + threadIdx.x;
    if (i < e) atomicAdd(&deg[src[i]], 1);
}

__global__ __launch_bounds__(256) void scan1_kernel(
    const int* __restrict__ deg, int* __restrict__ off, int* __restrict__ bsum, int n)
{
    __shared__ int wsum[8];
    const int tid  = threadIdx.x;
    const int lane = tid & 31, wid = tid >> 5;
    const int base = blockIdx.x * SCAN_TILE + tid * 16;

    int v[16];
    int tsum = 0;
#pragma unroll
    for (int i = 0; i < 16; i++) {
        const int gi = base + i;
        v[i] = (gi < n) ? deg[gi] : 0;
        tsum += v[i];
    }
    int x = tsum;
#pragma unroll
    for (int d = 1; d < 32; d <<= 1) {
        const int t = __shfl_up_sync(0xffffffffu, x, d);
        if (lane >= d) x += t;
    }
    if (lane == 31) wsum[wid] = x;
    __syncthreads();
    int wpre = 0;
#pragma unroll
    for (int w = 0; w < 8; w++) wpre += (w < wid) ? wsum[w] : 0;
    int run = wpre + x - tsum;
#pragma unroll
    for (int i = 0; i < 16; i++) {
        const int gi = base + i;
        if (gi < n) off[gi] = run;
        run += v[i];
    }
    if (tid == 255) bsum[blockIdx.x] = wpre + x;
}

__global__ __launch_bounds__(256) void scan2_kernel(
    const int* __restrict__ bsum, int* __restrict__ off, int n)
{
    __shared__ int pre_s, tot_s;
    if (threadIdx.x == 0) {
        int p = 0, t = 0;
#pragma unroll
        for (int b = 0; b < SCAN_BLOCKS; b++) {
            if (b < (int)blockIdx.x) p += bsum[b];
            t += bsum[b];
        }
        pre_s = p; tot_s = t;
    }
    __syncthreads();
    const int pre = pre_s;
    const int base = blockIdx.x * SCAN_TILE + threadIdx.x * 16;
#pragma unroll
    for (int i = 0; i < 16; i++) {
        const int gi = base + i;
        if (gi < n) off[gi] += pre;
    }
    if (blockIdx.x == 0 && threadIdx.x == 0) off[n] = tot_s;
}

__global__ void scatter_kernel(const int* __restrict__ src, const int* __restrict__ dst,
                               const int* __restrict__ off, int* __restrict__ cnt,
                               int* __restrict__ csr, int e) {
    const int i = blockIdx.x * blockDim.x + threadIdx.x;
    if (i < e) {
        const int s = src[i];
        const int pos = off[s] + atomicAdd(&cnt[s], 1);
        csr[pos] = dst[i];
    }
}

// warp per node: neigh[n] = sum over edges of h[dst] (fp16 rows, 256 B)
__global__ __launch_bounds__(256) void agg_kernel(
    const __half* __restrict__ h, const int* __restrict__ off,
    const int* __restrict__ csr, __half* __restrict__ neigh, int n)
{
    const int warp = (blockIdx.x * blockDim.x + threadIdx.x) >> 5;
    const int lane = threadIdx.x & 31;
    if (warp >= n) return;
    const int beg = off[warp], end = off[warp + 1];
    const int c0 = lane * 4;
    float4 acc0 = make_float4(0.f, 0.f, 0.f, 0.f);
    float4 acc1 = make_float4(0.f, 0.f, 0.f, 0.f);
    float4 acc2 = make_float4(0.f, 0.f, 0.f, 0.f);
    float4 acc3 = make_float4(0.f, 0.f, 0.f, 0.f);
    int e = beg;
    for (; e + 4 <= end; e += 4) {
        const int d0 = csr[e];
        const int d1 = csr[e + 1];
        const int d2 = csr[e + 2];
        const int d3 = csr[e + 3];
        const uint2 r0 = *(const uint2*)&h[(size_t)d0 * 128 + c0];
        const uint2 r1 = *(const uint2*)&h[(size_t)d1 * 128 + c0];
        const uint2 r2 = *(const uint2*)&h[(size_t)d2 * 128 + c0];
        const uint2 r3 = *(const uint2*)&h[(size_t)d3 * 128 + c0];
        {
            const float2 a = __half22float2(*reinterpret_cast<const __half2*>(&r0.x));
            const float2 b = __half22float2(*reinterpret_cast<const __half2*>(&r0.y));
            acc0.x += a.x; acc0.y += a.y; acc0.z += b.x; acc0.w += b.y;
        }
        {
            const float2 a = __half22float2(*reinterpret_cast<const __half2*>(&r1.x));
            const float2 b = __half22float2(*reinterpret_cast<const __half2*>(&r1.y));
            acc1.x += a.x; acc1.y += a.y; acc1.z += b.x; acc1.w += b.y;
        }
        {
            const float2 a = __half22float2(*reinterpret_cast<const __half2*>(&r2.x));
            const float2 b = __half22float2(*reinterpret_cast<const __half2*>(&r2.y));
            acc2.x += a.x; acc2.y += a.y; acc2.z += b.x; acc2.w += b.y;
        }
        {
            const float2 a = __half22float2(*reinterpret_cast<const __half2*>(&r3.x));
            const float2 b = __half22float2(*reinterpret_cast<const __half2*>(&r3.y));
            acc3.x += a.x; acc3.y += a.y; acc3.z += b.x; acc3.w += b.y;
        }
    }
    for (; e < end; e++) {
        const int d0 = csr[e];
        const uint2 r0 = *(const uint2*)&h[(size_t)d0 * 128 + c0];
        const float2 a = __half22float2(*reinterpret_cast<const __half2*>(&r0.x));
        const float2 b = __half22float2(*reinterpret_cast<const __half2*>(&r0.y));
        acc0.x += a.x; acc0.y += a.y; acc0.z += b.x; acc0.w += b.y;
    }
    acc0.x += acc1.x; acc0.y += acc1.y; acc0.z += acc1.z; acc0.w += acc1.w;
    acc2.x += acc3.x; acc2.y += acc3.y; acc2.z += acc3.z; acc2.w += acc3.w;
    acc0.x += acc2.x; acc0.y += acc2.y; acc0.z += acc2.z; acc0.w += acc2.w;
    uint2 o;
    *reinterpret_cast<__half2*>(&o.x) = __floats2half2_rn(acc0.x, acc0.y);
    *reinterpret_cast<__half2*>(&o.y) = __floats2half2_rn(acc0.z, acc0.w);
    *(uint2*)&neigh[(size_t)warp * 128 + c0] = o;
}

// ---------------- host orchestration ----------------
extern "C" void kernel_launch(void* const* d_in, const int* in_sizes, int n_in,
                              void* d_out, int out_size)
{
    const float* x       = (const float*)d_in[0];
    const int*   samples = (const int*)d_in[1];
    const int*   esrc    = (const int*)d_in[2];
    const int*   edst    = (const int*)d_in[3];
    const float* t_in_w  = (const float*)d_in[4];
    const float* t_in_b  = (const float*)d_in[5];
    const float* t_out_w = (const float*)d_in[6];
    const float* t_out_b = (const float*)d_in[7];
    const float* t_f_w1  = (const float*)d_in[8];
    const float* t_f_b1  = (const float*)d_in[9];
    const float* t_f_w2  = (const float*)d_in[10];
    const float* t_f_b2  = (const float*)d_in[11];
    const float* ln1g    = (const float*)d_in[12];
    const float* ln1b    = (const float*)d_in[13];
    const float* ln2g    = (const float*)d_in[14];
    const float* ln2b    = (const float*)d_in[15];
    const float* gw      = (const float*)d_in[16];
    const float* gb      = (const float*)d_in[17];
    const float* glng    = (const float*)d_in[18];
    const float* glnb    = (const float*)d_in[19];

    __half *pqkv, *pattn, *pa, *ptmp, *ph, *ph2, *pneigh, *phx;
    int *pdeg, *poff, *pcnt, *pcsr, *pbsum;
    __half *wqkv, *wout, *wf1, *wf2, *wg;
    float *bqkv, *bout, *bf1, *bf2, *l1g, *l1b, *l2g, *l2b, *bg, *gg, *gbv;
    cudaGetSymbolAddress((void**)&pqkv,   g_qkv);
    cudaGetSymbolAddress((void**)&pattn,  g_attn);
    cudaGetSymbolAddress((void**)&pa,     g_a);
    cudaGetSymbolAddress((void**)&ptmp,   g_tmp);
    cudaGetSymbolAddress((void**)&ph,     g_h);
    cudaGetSymbolAddress((void**)&ph2,    g_h2);
    cudaGetSymbolAddress((void**)&pneigh, g_neigh);
    cudaGetSymbolAddress((void**)&phx,    g_hx);
    cudaGetSymbolAddress((void**)&pdeg,   g_deg);
    cudaGetSymbolAddress((void**)&poff,   g_off);
    cudaGetSymbolAddress((void**)&pcnt,   g_cnt);
    cudaGetSymbolAddress((void**)&pcsr,   g_csr);
    cudaGetSymbolAddress((void**)&pbsum,  g_bsum);
    cudaGetSymbolAddress((void**)&wqkv,   g_wqkv);
    cudaGetSymbolAddress((void**)&wout,   g_wout);
    cudaGetSymbolAddress((void**)&wf1,    g_wf1);
    cudaGetSymbolAddress((void**)&wf2,    g_wf2);
    cudaGetSymbolAddress((void**)&wg,     g_wg);
    cudaGetSymbolAddress((void**)&bqkv,   g_bqkv);
    cudaGetSymbolAddress((void**)&bout,   g_bout);
    cudaGetSymbolAddress((void**)&bf1,    g_bf1);
    cudaGetSymbolAddress((void**)&bf2,    g_bf2);
    cudaGetSymbolAddress((void**)&l1g,    g_l1g);
    cudaGetSymbolAddress((void**)&l1b,    g_l1b);
    cudaGetSymbolAddress((void**)&l2g,    g_l2g);
    cudaGetSymbolAddress((void**)&l2b,    g_l2b);
    cudaGetSymbolAddress((void**)&bg,     g_bg);
    cudaGetSymbolAddress((void**)&gg,     g_gg);
    cudaGetSymbolAddress((void**)&gbv,    g_gb);

    const int n = NN;
    const int e = EE;
    const int GX = (n + 127) / 128;
    const int WARP_GRID = (n + 7) / 8;
    const int EG = (e + 255) / 256;
    const size_t SMEMSZ = (size_t)4 * 128 * 80 * sizeof(__half) + 256 * sizeof(float2);

    cudaFuncSetAttribute(gemm_f16<128, 384, false, false, false, false, 1>,
                         cudaFuncAttributeMaxDynamicSharedMemorySize, (int)SMEMSZ);
    cudaFuncSetAttribute(gemm_f16<128, 128, false, true, true, false, 1>,
                         cudaFuncAttributeMaxDynamicSharedMemorySize, (int)SMEMSZ);
    cudaFuncSetAttribute(gemm_f16<128, 512, true, false, false, false, 1>,
                         cudaFuncAttributeMaxDynamicSharedMemorySize, (int)SMEMSZ);
    cudaFuncSetAttribute(gemm_f16<512, 128, false, true, true, false, 1>,
                         cudaFuncAttributeMaxDynamicSharedMemorySize, (int)SMEMSZ);
    cudaFuncSetAttribute(gemm_f16<512, 128, false, true, true, false, 2>,
                         cudaFuncAttributeMaxDynamicSharedMemorySize, (int)SMEMSZ);
    cudaFuncSetAttribute(gemm_f16<256, 128, true, true, true, true, 1>,
                         cudaFuncAttributeMaxDynamicSharedMemorySize, (int)SMEMSZ);

    // side stream + events (created once; graph fork/join pattern)
    static cudaStream_t sB = nullptr;
    static cudaEvent_t evFork = nullptr, evJoin = nullptr;
    if (sB == nullptr) {
        cudaStreamCreateWithFlags(&sB, cudaStreamNonBlocking);
        cudaEventCreateWithFlags(&evFork, cudaEventDisableTiming);
        cudaEventCreateWithFlags(&evJoin, cudaEventDisableTiming);
    }

    // ---- parameter conversion tables ----
    PTab tabA; int na = 0;
    tabA.e[na++] = { t_in_w,  wqkv, 384, 128, 0 };
    tabA.e[na++] = { t_out_w, wout, 128, 128, 0 };
    tabA.e[na++] = { t_f_w1,  wf1,  512, 128, 0 };
    tabA.e[na++] = { t_f_w2,  wf2,  128, 512, 0 };
    tabA.e[na++] = { t_in_b,  bqkv, 1, 384, 1 };
    tabA.e[na++] = { t_out_b, bout, 1, 128, 1 };
    tabA.e[na++] = { t_f_b1,  bf1,  1, 512, 1 };
    tabA.e[na++] = { t_f_b2,  bf2,  1, 128, 1 };
    tabA.e[na++] = { ln1g, l1g, 1, 128, 1 };
    tabA.e[na++] = { ln1b, l1b, 1, 128, 1 };
    tabA.e[na++] = { ln2g, l2g, 1, 128, 1 };
    tabA.e[na++] = { ln2b, l2b, 1, 128, 1 };
    PTab tabB; int nb = 0;
    for (int i = 1; i < 3; i++) {
        tabB.e[nb++] = { t_in_w  + (size_t)i * 384 * 128, wqkv + (size_t)i * 384 * 128, 384, 128, 0 };
        tabB.e[nb++] = { t_out_w + (size_t)i * 128 * 128, wout + (size_t)i * 128 * 128, 128, 128, 0 };
        tabB.e[nb++] = { t_f_w1  + (size_t)i * 512 * 128, wf1  + (size_t)i * 512 * 128, 512, 128, 0 };
        tabB.e[nb++] = { t_f_w2  + (size_t)i * 128 * 512, wf2  + (size_t)i * 128 * 512, 128, 512, 0 };
        tabB.e[nb++] = { t_in_b  + i * 384, bqkv + i * 384, 1, 384, 1 };
        tabB.e[nb++] = { t_out_b + i * 128, bout + i * 128, 1, 128, 1 };
        tabB.e[nb++] = { t_f_b1  + i * 512, bf1  + i * 512, 1, 512, 1 };
        tabB.e[nb++] = { t_f_b2  + i * 128, bf2  + i * 128, 1, 128, 1 };
        tabB.e[nb++] = { ln1g + i * 128, l1g + i * 128, 1, 128, 1 };
        tabB.e[nb++] = { ln1b + i * 128, l1b + i * 128, 1, 128, 1 };
        tabB.e[nb++] = { ln2g + i * 128, l2g + i * 128, 1, 128, 1 };
        tabB.e[nb++] = { ln2b + i * 128, l2b + i * 128, 1, 128, 1 };
    }
    for (int i = 0; i < 2; i++) {
        tabB.e[nb++] = { gw + (size_t)i * 128 * 256, wg + (size_t)i * 128 * 256, 128, 256, 0 };
        tabB.e[nb++] = { gb   + i * 128, bg  + i * 128, 1, 128, 1 };
        tabB.e[nb++] = { glng + i * 128, gg  + i * 128, 1, 128, 1 };
        tabB.e[nb++] = { glnb + i * 128, gbv + i * 128, 1, 128, 1 };
    }

    // fork point: side work depends only on inputs
    cudaEventRecord(evFork, 0);
    cudaStreamWaitEvent(sB, evFork, 0);

    // ---- main stream: critical conversions + trans1 ----
    param_conv<<<dim3(64, na), 256>>>(tabA, na);
    conv_x<<<(NN * 128 + 255) / 256, 256>>>(x, phx);

    // ---- side stream: rest of params + CSR build (overlaps trans1) ----
    param_conv<<<dim3(64, nb), 256, 0, sB>>>(tabB, nb);
    zero_kernel<<<(n + 255) / 256, 256, 0, sB>>>(pdeg, pcnt, n);
    hist_kernel<<<EG, 256, 0, sB>>>(esrc, pdeg, e);
    scan1_kernel<<<SCAN_BLOCKS, 256, 0, sB>>>(pdeg, poff, pbsum, n);
    scan2_kernel<<<SCAN_BLOCKS, 256, 0, sB>>>(pbsum, poff, n);
    scatter_kernel<<<EG, 256, 0, sB>>>(esrc, edst, poff, pcnt, pcsr, e);
    cudaEventRecord(evJoin, sB);

    // ---- transformer layer ----
    auto run_trans = [&](const __half* hin, __half* hout, int i, bool final_layer) {
        gemm_f16<128, 384, false, false, false, false, 1><<<dim3(GX, 3), 256, SMEMSZ>>>(
            hin, nullptr, wqkv + (size_t)i * 384 * 128, bqkv + i * 384,
            nullptr, nullptr, nullptr, pqkv, nullptr, n);
        attn_kernel<<<WARP_GRID, 256>>>(pqkv, samples, pattn, n);
        gemm_f16<128, 128, false, true, true, false, 1><<<dim3(GX, 1), 256, SMEMSZ>>>(
            pattn, nullptr, wout + (size_t)i * 128 * 128, bout + i * 128,
            hin, l1g + i * 128, l1b + i * 128, pa, nullptr, n);
        gemm_f16<128, 512, true, false, false, false, 1><<<dim3(GX, 4), 256, SMEMSZ>>>(
            pa, nullptr, wf1 + (size_t)i * 512 * 128, bf1 + i * 512,
            nullptr, nullptr, nullptr, ptmp, nullptr, n);
        if (final_layer) {
            gemm_f16<512, 128, false, true, true, false, 2><<<dim3(GX, 1), 256, SMEMSZ>>>(
                ptmp, nullptr, wf2 + (size_t)i * 128 * 512, bf2 + i * 128,
                pa, l2g + i * 128, l2b + i * 128, nullptr, (float*)d_out, n);
        } else {
            gemm_f16<512, 128, false, true, true, false, 1><<<dim3(GX, 1), 256, SMEMSZ>>>(
                ptmp, nullptr, wf2 + (size_t)i * 128 * 512, bf2 + i * 128,
                pa, l2g + i * 128, l2b + i * 128, hout, nullptr, n);
        }
    };

    auto run_gnn = [&](const __half* hin, __half* hout, int i) {
        agg_kernel<<<WARP_GRID, 256>>>(hin, poff, pcsr, pneigh, n);
        gemm_f16<256, 128, true, true, true, true, 1><<<dim3(GX, 1), 256, SMEMSZ>>>(
            hin, pneigh, wg + (size_t)i * 128 * 256, bg + i * 128,
            hin, gg + i * 128, gbv + i * 128, hout, nullptr, n);
    };

    run_trans(phx, ph, 0, false);

    // join before first aggregation
    cudaStreamWaitEvent(0, evJoin, 0);

    run_gnn(ph, ph2, 0);
    run_trans(ph2, ph, 1, false);
    run_gnn(ph, ph2, 1);
    run_trans(ph2, nullptr, 2, true);
}

// round 13
// speedup vs baseline: 1.0079x; 1.0021x over previous
#include <cuda_runtime.h>
#include <cuda_fp16.h>

#define NN 50000
#define DD 128
#define EE 1600000
#define KATT 20
#define SCAN_TILE 4096
#define SCAN_BLOCKS ((NN + SCAN_TILE - 1) / SCAN_TILE)

// ---------------- scratch (static device allocations) ----------------
__device__ __half g_qkv[NN * 384];
__device__ __half g_attn[NN * DD];
__device__ __half g_a[NN * DD];
__device__ __half g_tmp[NN * 512];
__device__ __half g_h[NN * DD];
__device__ __half g_h2[NN * DD];
__device__ __half g_neigh[NN * DD];
__device__ __half g_hx[NN * DD];
__device__ int   g_deg[NN];
__device__ int   g_off[NN + 1];
__device__ int   g_cnt[NN];
__device__ int   g_csr[EE];
__device__ int   g_bsum[SCAN_BLOCKS];

// converted (fp16, pair-permuted) weights; fp32 permuted biases/LN params
__device__ __half g_wqkv[3 * 384 * 128];
__device__ __half g_wout[3 * 128 * 128];
__device__ __half g_wf1 [3 * 512 * 128];
__device__ __half g_wf2 [3 * 128 * 512];
__device__ __half g_wg  [2 * 128 * 256];
__device__ float g_bqkv[3 * 384];
__device__ float g_bout[3 * 128];
__device__ float g_bf1 [3 * 512];
__device__ float g_bf2 [3 * 128];
__device__ float g_l1g [3 * 128];
__device__ float g_l1b [3 * 128];
__device__ float g_l2g [3 * 128];
__device__ float g_l2b [3 * 128];
__device__ float g_bg  [2 * 128];
__device__ float g_gg  [2 * 128];
__device__ float g_gb  [2 * 128];

// ---------------- helpers ----------------
// within-16 column PAIR permutation (logical -> physical):
// pair p (cols 2p,2p+1) -> np = ((p&3)<<1)|(p>>2). Keeps pairs adjacent so
// thread t's mma k-halves {2t,2t+1} and {2t+8,2t+9} form one 8B word.
__device__ __forceinline__ int gperm16(int i) {
    const int p  = (i >> 1) & 7;
    const int o  = i & 1;
    const int np = ((p & 3) << 1) | (p >> 2);
    return (i & ~15) | (np << 1) | o;
}
// inverse (physical -> logical)
__device__ __forceinline__ int igperm16(int c) {
    const int np = (c >> 1) & 7;
    const int o  = c & 1;
    const int p  = ((np >> 1) & 3) | ((np & 1) << 2);
    return (c & ~15) | (p << 1) | o;
}

__device__ __forceinline__ void mma_f16(float c[4], unsigned a0, unsigned a1,
                                        unsigned a2, unsigned a3,
                                        unsigned b0, unsigned b1) {
    asm("mma.sync.aligned.m16n8k16.row.col.f32.f16.f16.f32 "
        "{%0,%1,%2,%3}, {%4,%5,%6,%7}, {%8,%9}, {%0,%1,%2,%3};\n"
        : "+f"(c[0]), "+f"(c[1]), "+f"(c[2]), "+f"(c[3])
        : "r"(a0), "r"(a1), "r"(a2), "r"(a3), "r"(b0), "r"(b1));
}

__device__ __forceinline__ void cp16(void* sdst, const void* gsrc, int sz) {
    unsigned s = (unsigned)__cvta_generic_to_shared(sdst);
    asm volatile("cp.async.cg.shared.global [%0], [%1], 16, %2;\n"
                 :: "r"(s), "l"(gsrc), "r"(sz));
}
__device__ __forceinline__ void cp_commit() {
    asm volatile("cp.async.commit_group;\n");
}
__device__ __forceinline__ void cp_wait1() {
    asm volatile("cp.async.wait_group 1;\n");
}
__device__ __forceinline__ void cp_wait0() {
    asm volatile("cp.async.wait_group 0;\n");
}

// ---------------- parameter conversion ----------------
struct PEnt { const float* s; void* d; int rows; int cols; int mode; };
struct PTab { PEnt e[32]; };

__global__ void param_conv(PTab t, int n) {
    const int ei = blockIdx.y;
    if (ei >= n) return;
    const PEnt en = t.e[ei];
    const int total = en.rows * en.cols;
    for (int i = blockIdx.x * blockDim.x + threadIdx.x; i < total;
         i += gridDim.x * blockDim.x) {
        if (en.mode == 0) {           // matrix: permute both dims, fp16
            const int r = i / en.cols, c = i % en.cols;
            ((__half*)en.d)[(size_t)gperm16(r) * en.cols + gperm16(c)] =
                __float2half_rn(en.s[i]);
        } else {                      // vector: permute only, fp32
            ((float*)en.d)[gperm16(i)] = en.s[i];
        }
    }
}

__global__ void conv_x(const float* __restrict__ x, __half* __restrict__ o) {
    const int i = blockIdx.x * blockDim.x + threadIdx.x;
    if (i < NN * 128) {
        const int r = i >> 7, c = i & 127;
        o[(r << 7) + gperm16(c)] = __float2half_rn(x[i]);
    }
}

// ---------------- fused FP16 tensor-core GEMM (cp.async pipelined) ----------------
// All operands fp16 in permuted world. Block 128x128, 8 warps (4m x 2n),
// warp tile 32x64, BK=64 halves, 2-stage cp.async. Smem row stride 160B
// (conflict-free 8B fragment loads). Accum fp32, epilogue fp32.
// OMODE 1: store fp16. OMODE 2: final fp32 store with inverse column perm.
template <int IN, int OUT, bool RELU, bool RES, bool LN, bool SPLIT, int OMODE>
__global__ __launch_bounds__(256, 2) void gemm_f16(
    const __half* __restrict__ A, const __half* __restrict__ A2,
    const __half* __restrict__ W, const float* __restrict__ bias,
    const __half* __restrict__ res,
    const float* __restrict__ lng, const float* __restrict__ lnb,
    __half* __restrict__ Ch, float* __restrict__ Cf, int nrows)
{
    constexpr int SSTH = 80;                     // smem row stride in halves
    extern __shared__ __half smemh[];
    __half* Asm[2] = { smemh,               smemh + 128 * SSTH };
    __half* Wsm[2] = { smemh + 2 * 128 * SSTH, smemh + 3 * 128 * SSTH };
    float2* lnp    = (float2*)(smemh + 4 * 128 * SSTH);   // [2][128]

    const int tid    = threadIdx.x;
    const int lane   = tid & 31;
    const int warp   = tid >> 5;
    const int warp_m = warp & 3;
    const int warp_n = warp >> 2;
    const int g      = lane >> 2;
    const int t      = lane & 3;
    const int row0   = blockIdx.x * 128;
    const int col0   = blockIdx.y * 128;
    const int colb   = warp_n * 64;

    float acc[2][8][4];
#pragma unroll
    for (int fm = 0; fm < 2; fm++)
#pragma unroll
        for (int nf = 0; nf < 8; nf++)
#pragma unroll
            for (int r = 0; r < 4; r++) acc[fm][nf][r] = 0.f;

    constexpr int NCH = IN / 64;

    auto issue = [&](int chunk, int st) {
        const int kc = chunk * 64;               // halves
        __half* as = Asm[st];
        __half* ws = Wsm[st];
#pragma unroll
        for (int it = 0; it < 8; it++) {
            const int idx = it * 256 + tid;      // 0..2047
            const int r   = (idx >> 3) & 127;
            const int c   = idx & 7;             // 16B chunk = 8 halves
            const int kk  = kc + c * 8;
            if (idx < 1024) {
                const int grow = row0 + r;
                const bool ok  = (grow < nrows);
                const int crow = ok ? grow : 0;
                const __half* ap;
                if (SPLIT) {
                    ap = (kk < 128) ? &A[(size_t)crow * 128 + kk]
                                    : &A2[(size_t)crow * 128 + (kk - 128)];
                } else {
                    ap = &A[(size_t)crow * IN + kk];
                }
                cp16(as + r * SSTH + c * 8, ap, ok ? 16 : 0);
            } else {
                cp16(ws + r * SSTH + c * 8, &W[(size_t)(col0 + r) * IN + kk], 16);
            }
        }
        cp_commit();
    };

    auto compute = [&](int st) {
        const __half* as = Asm[st];
        const __half* ws = Wsm[st];
#pragma unroll
        for (int ks = 0; ks < 4; ks++) {
            const int kw = ks * 16 + 4 * t;      // halves offset
            unsigned a[2][4];
#pragma unroll
            for (int fm = 0; fm < 2; fm++) {
                const int rb = warp_m * 32 + fm * 16;
                const uint2 lo = *(const uint2*)(as + (rb + g) * SSTH + kw);
                const uint2 hi = *(const uint2*)(as + (rb + g + 8) * SSTH + kw);
                a[fm][0] = lo.x; a[fm][1] = hi.x;   // (r,k0k1), (r+8,k0k1)
                a[fm][2] = lo.y; a[fm][3] = hi.y;   // (r,k8k9), (r+8,k8k9)
            }
#pragma unroll
            for (int nf = 0; nf < 8; nf++) {
                const uint2 bb = *(const uint2*)(ws + (colb + nf * 8 + g) * SSTH + kw);
                mma_f16(acc[0][nf], a[0][0], a[0][1], a[0][2], a[0][3], bb.x, bb.y);
                mma_f16(acc[1][nf], a[1][0], a[1][1], a[1][2], a[1][3], bb.x, bb.y);
            }
        }
    };

    issue(0, 0);
#pragma unroll 1
    for (int ch = 0; ch < NCH; ch++) {
        if (ch + 1 < NCH) {
            issue(ch + 1, (ch + 1) & 1);
            cp_wait1();
        } else {
            cp_wait0();
        }
        __syncthreads();
        compute(ch & 1);
        __syncthreads();
    }

    // ---------------- epilogue ----------------
    float2 bias2[8];
#pragma unroll
    for (int nf = 0; nf < 8; nf++)
        bias2[nf] = *(const float2*)&bias[col0 + colb + nf * 8 + 2 * t];

#pragma unroll
    for (int fm = 0; fm < 2; fm++) {
#pragma unroll
        for (int ro = 0; ro < 2; ro++) {
            const int row  = warp_m * 32 + fm * 16 + ro * 8 + g;
            const int grow = row0 + row;
            const bool ok  = (grow < nrows);
            float s = 0.f, s2 = 0.f;
#pragma unroll
            for (int nf = 0; nf < 8; nf++) {
                float v0 = acc[fm][nf][ro * 2 + 0] + bias2[nf].x;
                float v1 = acc[fm][nf][ro * 2 + 1] + bias2[nf].y;
                if (RELU) { v0 = fmaxf(v0, 0.f); v1 = fmaxf(v1, 0.f); }
                if (RES && ok) {
                    const __half2 rh = *(const __half2*)
                        &res[(size_t)grow * OUT + col0 + colb + nf * 8 + 2 * t];
                    const float2 rv = __half22float2(rh);
                    v0 += rv.x; v1 += rv.y;
                }
                acc[fm][nf][ro * 2 + 0] = v0;
                acc[fm][nf][ro * 2 + 1] = v1;
                if (LN) { s += v0 + v1; s2 += v0 * v0 + v1 * v1; }
            }
            if (LN) {
                s  += __shfl_xor_sync(0xffffffffu, s, 1);
                s2 += __shfl_xor_sync(0xffffffffu, s2, 1);
                s  += __shfl_xor_sync(0xffffffffu, s, 2);
                s2 += __shfl_xor_sync(0xffffffffu, s2, 2);
                if (t == 0) lnp[warp_n * 128 + row] = make_float2(s, s2);
            }
        }
    }
    if (LN) __syncthreads();

#pragma unroll
    for (int fm = 0; fm < 2; fm++) {
#pragma unroll
        for (int ro = 0; ro < 2; ro++) {
            const int row  = warp_m * 32 + fm * 16 + ro * 8 + g;
            const int grow = row0 + row;
            if (grow >= nrows) continue;
            float mean = 0.f, rstd = 1.f;
            if (LN) {
                const float2 p0 = lnp[row];
                const float2 p1 = lnp[128 + row];
                const float s  = p0.x + p1.x;
                const float s2 = p0.y + p1.y;
                mean = s * (1.f / 128.f);
                const float var = s2 * (1.f / 128.f) - mean * mean;
                rstd = rsqrtf(var + 1e-5f);
            }
#pragma unroll
            for (int nf = 0; nf < 8; nf++) {
                const int col = col0 + colb + nf * 8 + 2 * t;
                float v0 = acc[fm][nf][ro * 2 + 0];
                float v1 = acc[fm][nf][ro * 2 + 1];
                if (LN) {
                    const float2 gv = *(const float2*)&lng[col];
                    const float2 bb = *(const float2*)&lnb[col];
                    v0 = (v0 - mean) * rstd * gv.x + bb.x;
                    v1 = (v1 - mean) * rstd * gv.y + bb.y;
                }
                if (OMODE == 1) {
                    *(__half2*)&Ch[(size_t)grow * OUT + col] =
                        __floats2half2_rn(v0, v1);
                } else {
                    Cf[(size_t)grow * OUT + igperm16(col)]     = v0;
                    Cf[(size_t)grow * OUT + igperm16(col + 1)] = v1;
                }
            }
        }
    }
}

// ---------------- attention: warp per node, single-pass, fp16 qkv ------------
// Scores tiny (LN'd inputs x 0.02 weights) -> exp without max-shift is safe.
__global__ __launch_bounds__(256) void attn_kernel(
    const __half* __restrict__ qkv, const int* __restrict__ samp,
    __half* __restrict__ out, int n)
{
    const int warp = (blockIdx.x * blockDim.x + threadIdx.x) >> 5;
    const int lane = threadIdx.x & 31;
    if (warp >= n) return;
    const int node = warp;
    const int c0 = lane * 4;
    const float scale = 0.17677669529663687f;   // 1/sqrt(32)

    const uint2 qraw = *(const uint2*)&qkv[(size_t)node * 384 + c0];
    const float2 q01 = __half22float2(*reinterpret_cast<const __half2*>(&qraw.x));
    const float2 q23 = __half22float2(*reinterpret_cast<const __half2*>(&qraw.y));
    float sum = 0.f;
    float4 acc = make_float4(0.f, 0.f, 0.f, 0.f);

#pragma unroll
    for (int j0 = 0; j0 < KATT; j0 += 4) {
        int id[4];
#pragma unroll
        for (int jj = 0; jj < 4; jj++)
            id[jj] = __ldg(&samp[node * KATT + j0 + jj]);
        uint2 kraw[4], vraw[4];
#pragma unroll
        for (int jj = 0; jj < 4; jj++) {
            const size_t base = (size_t)id[jj] * 384 + c0;
            kraw[jj] = *(const uint2*)&qkv[base + 128];
            vraw[jj] = *(const uint2*)&qkv[base + 256];
        }
#pragma unroll
        for (int jj = 0; jj < 4; jj++) {
            const float2 k01 = __half22float2(
                *reinterpret_cast<const __half2*>(&kraw[jj].x));
            const float2 k23 = __half22float2(
                *reinterpret_cast<const __half2*>(&kraw[jj].y));
            float d = q01.x * k01.x + q01.y * k01.y + q23.x * k23.x + q23.y * k23.y;
            d += __shfl_xor_sync(0xffffffffu, d, 1);
            d += __shfl_xor_sync(0xffffffffu, d, 2);
            d += __shfl_xor_sync(0xffffffffu, d, 4);
            const float e = __expf(d * scale);
            sum += e;
            const float2 v01 = __half22float2(
                *reinterpret_cast<const __half2*>(&vraw[jj].x));
            const float2 v23 = __half22float2(
                *reinterpret_cast<const __half2*>(&vraw[jj].y));
            acc.x += e * v01.x; acc.y += e * v01.y;
            acc.z += e * v23.x; acc.w += e * v23.y;
        }
    }
    const float inv = 1.f / sum;
    uint2 o;
    *reinterpret_cast<__half2*>(&o.x) = __floats2half2_rn(acc.x * inv, acc.y * inv);
    *reinterpret_cast<__half2*>(&o.y) = __floats2half2_rn(acc.z * inv, acc.w * inv);
    *(uint2*)&out[(size_t)node * 128 + c0] = o;
}

// ---------------- GNN CSR build + aggregate ----------------
__global__ void zero_kernel(int* __restrict__ a, int* __restrict__ b, int n) {
    const int i = blockIdx.x * blockDim.x + threadIdx.x;
    if (i < n) { a[i] = 0; b[i] = 0; }
}

__global__ void hist_kernel(const int* __restrict__ src, int* __restrict__ deg, int e) {
    const int i = blockIdx.x * blockDim.x + threadIdx.x;
    if (i < e) atomicAdd(&deg[src[i]], 1);
}

__global__ __launch_bounds__(256) void scan1_kernel(
    const int* __restrict__ deg, int* __restrict__ off, int* __restrict__ bsum, int n)
{
    __shared__ int wsum[8];
    const int tid  = threadIdx.x;
    const int lane = tid & 31, wid = tid >> 5;
    const int base = blockIdx.x * SCAN_TILE + tid * 16;

    int v[16];
    int tsum = 0;
#pragma unroll
    for (int i = 0; i < 16; i++) {
        const int gi = base + i;
        v[i] = (gi < n) ? deg[gi] : 0;
        tsum += v[i];
    }
    int x = tsum;
#pragma unroll
    for (int d = 1; d < 32; d <<= 1) {
        const int t = __shfl_up_sync(0xffffffffu, x, d);
        if (lane >= d) x += t;
    }
    if (lane == 31) wsum[wid] = x;
    __syncthreads();
    int wpre = 0;
#pragma unroll
    for (int w = 0; w < 8; w++) wpre += (w < wid) ? wsum[w] : 0;
    int run = wpre + x - tsum;
#pragma unroll
    for (int i = 0; i < 16; i++) {
        const int gi = base + i;
        if (gi < n) off[gi] = run;
        run += v[i];
    }
    if (tid == 255) bsum[blockIdx.x] = wpre + x;
}

__global__ __launch_bounds__(256) void scan2_kernel(
    const int* __restrict__ bsum, int* __restrict__ off, int n)
{
    __shared__ int pre_s, tot_s;
    if (threadIdx.x == 0) {
        int p = 0, t = 0;
#pragma unroll
        for (int b = 0; b < SCAN_BLOCKS; b++) {
            if (b < (int)blockIdx.x) p += bsum[b];
            t += bsum[b];
        }
        pre_s = p; tot_s = t;
    }
    __syncthreads();
    const int pre = pre_s;
    const int base = blockIdx.x * SCAN_TILE + threadIdx.x * 16;
#pragma unroll
    for (int i = 0; i < 16; i++) {
        const int gi = base + i;
        if (gi < n) off[gi] += pre;
    }
    if (blockIdx.x == 0 && threadIdx.x == 0) off[n] = tot_s;
}

__global__ void scatter_kernel(const int* __restrict__ src, const int* __restrict__ dst,
                               const int* __restrict__ off, int* __restrict__ cnt,
                               int* __restrict__ csr, int e) {
    const int i = blockIdx.x * blockDim.x + threadIdx.x;
    if (i < e) {
        const int s = src[i];
        const int pos = off[s] + atomicAdd(&cnt[s], 1);
        csr[pos] = dst[i];
    }
}

// warp per node: neigh[n] = sum over edges of h[dst] (fp16 rows, 256 B)
__global__ __launch_bounds__(256) void agg_kernel(
    const __half* __restrict__ h, const int* __restrict__ off,
    const int* __restrict__ csr, __half* __restrict__ neigh, int n)
{
    const int warp = (blockIdx.x * blockDim.x + threadIdx.x) >> 5;
    const int lane = threadIdx.x & 31;
    if (warp >= n) return;
    const int beg = off[warp], end = off[warp + 1];
    const int c0 = lane * 4;
    float4 acc0 = make_float4(0.f, 0.f, 0.f, 0.f);
    float4 acc1 = make_float4(0.f, 0.f, 0.f, 0.f);
    float4 acc2 = make_float4(0.f, 0.f, 0.f, 0.f);
    float4 acc3 = make_float4(0.f, 0.f, 0.f, 0.f);
    int e = beg;
    for (; e + 4 <= end; e += 4) {
        const int d0 = csr[e];
        const int d1 = csr[e + 1];
        const int d2 = csr[e + 2];
        const int d3 = csr[e + 3];
        const uint2 r0 = *(const uint2*)&h[(size_t)d0 * 128 + c0];
        const uint2 r1 = *(const uint2*)&h[(size_t)d1 * 128 + c0];
        const uint2 r2 = *(const uint2*)&h[(size_t)d2 * 128 + c0];
        const uint2 r3 = *(const uint2*)&h[(size_t)d3 * 128 + c0];
        {
            const float2 a = __half22float2(*reinterpret_cast<const __half2*>(&r0.x));
            const float2 b = __half22float2(*reinterpret_cast<const __half2*>(&r0.y));
            acc0.x += a.x; acc0.y += a.y; acc0.z += b.x; acc0.w += b.y;
        }
        {
            const float2 a = __half22float2(*reinterpret_cast<const __half2*>(&r1.x));
            const float2 b = __half22float2(*reinterpret_cast<const __half2*>(&r1.y));
            acc1.x += a.x; acc1.y += a.y; acc1.z += b.x; acc1.w += b.y;
        }
        {
            const float2 a = __half22float2(*reinterpret_cast<const __half2*>(&r2.x));
            const float2 b = __half22float2(*reinterpret_cast<const __half2*>(&r2.y));
            acc2.x += a.x; acc2.y += a.y; acc2.z += b.x; acc2.w += b.y;
        }
        {
            const float2 a = __half22float2(*reinterpret_cast<const __half2*>(&r3.x));
            const float2 b = __half22float2(*reinterpret_cast<const __half2*>(&r3.y));
            acc3.x += a.x; acc3.y += a.y; acc3.z += b.x; acc3.w += b.y;
        }
    }
    for (; e < end; e++) {
        const int d0 = csr[e];
        const uint2 r0 = *(const uint2*)&h[(size_t)d0 * 128 + c0];
        const float2 a = __half22float2(*reinterpret_cast<const __half2*>(&r0.x));
        const float2 b = __half22float2(*reinterpret_cast<const __half2*>(&r0.y));
        acc0.x += a.x; acc0.y += a.y; acc0.z += b.x; acc0.w += b.y;
    }
    acc0.x += acc1.x; acc0.y += acc1.y; acc0.z += acc1.z; acc0.w += acc1.w;
    acc2.x += acc3.x; acc2.y += acc3.y; acc2.z += acc3.z; acc2.w += acc3.w;
    acc0.x += acc2.x; acc0.y += acc2.y; acc0.z += acc2.z; acc0.w += acc2.w;
    uint2 o;
    *reinterpret_cast<__half2*>(&o.x) = __floats2half2_rn(acc0.x, acc0.y);
    *reinterpret_cast<__half2*>(&o.y) = __floats2half2_rn(acc0.z, acc0.w);
    *(uint2*)&neigh[(size_t)warp * 128 + c0] = o;
}

// ---------------- host orchestration ----------------
extern "C" void kernel_launch(void* const* d_in, const int* in_sizes, int n_in,
                              void* d_out, int out_size)
{
    const float* x       = (const float*)d_in[0];
    const int*   samples = (const int*)d_in[1];
    const int*   esrc    = (const int*)d_in[2];
    const int*   edst    = (const int*)d_in[3];
    const float* t_in_w  = (const float*)d_in[4];
    const float* t_in_b  = (const float*)d_in[5];
    const float* t_out_w = (const float*)d_in[6];
    const float* t_out_b = (const float*)d_in[7];
    const float* t_f_w1  = (const float*)d_in[8];
    const float* t_f_b1  = (const float*)d_in[9];
    const float* t_f_w2  = (const float*)d_in[10];
    const float* t_f_b2  = (const float*)d_in[11];
    const float* ln1g    = (const float*)d_in[12];
    const float* ln1b    = (const float*)d_in[13];
    const float* ln2g    = (const float*)d_in[14];
    const float* ln2b    = (const float*)d_in[15];
    const float* gw      = (const float*)d_in[16];
    const float* gb      = (const float*)d_in[17];
    const float* glng    = (const float*)d_in[18];
    const float* glnb    = (const float*)d_in[19];

    __half *pqkv, *pattn, *pa, *ptmp, *ph, *ph2, *pneigh, *phx;
    int *pdeg, *poff, *pcnt, *pcsr, *pbsum;
    __half *wqkv, *wout, *wf1, *wf2, *wg;
    float *bqkv, *bout, *bf1, *bf2, *l1g, *l1b, *l2g, *l2b, *bg, *gg, *gbv;
    cudaGetSymbolAddress((void**)&pqkv,   g_qkv);
    cudaGetSymbolAddress((void**)&pattn,  g_attn);
    cudaGetSymbolAddress((void**)&pa,     g_a);
    cudaGetSymbolAddress((void**)&ptmp,   g_tmp);
    cudaGetSymbolAddress((void**)&ph,     g_h);
    cudaGetSymbolAddress((void**)&ph2,    g_h2);
    cudaGetSymbolAddress((void**)&pneigh, g_neigh);
    cudaGetSymbolAddress((void**)&phx,    g_hx);
    cudaGetSymbolAddress((void**)&pdeg,   g_deg);
    cudaGetSymbolAddress((void**)&poff,   g_off);
    cudaGetSymbolAddress((void**)&pcnt,   g_cnt);
    cudaGetSymbolAddress((void**)&pcsr,   g_csr);
    cudaGetSymbolAddress((void**)&pbsum,  g_bsum);
    cudaGetSymbolAddress((void**)&wqkv,   g_wqkv);
    cudaGetSymbolAddress((void**)&wout,   g_wout);
    cudaGetSymbolAddress((void**)&wf1,    g_wf1);
    cudaGetSymbolAddress((void**)&wf2,    g_wf2);
    cudaGetSymbolAddress((void**)&wg,     g_wg);
    cudaGetSymbolAddress((void**)&bqkv,   g_bqkv);
    cudaGetSymbolAddress((void**)&bout,   g_bout);
    cudaGetSymbolAddress((void**)&bf1,    g_bf1);
    cudaGetSymbolAddress((void**)&bf2,    g_bf2);
    cudaGetSymbolAddress((void**)&l1g,    g_l1g);
    cudaGetSymbolAddress((void**)&l1b,    g_l1b);
    cudaGetSymbolAddress((void**)&l2g,    g_l2g);
    cudaGetSymbolAddress((void**)&l2b,    g_l2b);
    cudaGetSymbolAddress((void**)&bg,     g_bg);
    cudaGetSymbolAddress((void**)&gg,     g_gg);
    cudaGetSymbolAddress((void**)&gbv,    g_gb);

    const int n = NN;
    const int e = EE;
    const int GX = (n + 127) / 128;
    const int WARP_GRID = (n + 7) / 8;
    const int EG = (e + 255) / 256;
    const size_t SMEMSZ = (size_t)4 * 128 * 80 * sizeof(__half) + 256 * sizeof(float2);

    cudaFuncSetAttribute(gemm_f16<128, 384, false, false, false, false, 1>,
                         cudaFuncAttributeMaxDynamicSharedMemorySize, (int)SMEMSZ);
    cudaFuncSetAttribute(gemm_f16<128, 128, false, true, true, false, 1>,
                         cudaFuncAttributeMaxDynamicSharedMemorySize, (int)SMEMSZ);
    cudaFuncSetAttribute(gemm_f16<128, 512, true, false, false, false, 1>,
                         cudaFuncAttributeMaxDynamicSharedMemorySize, (int)SMEMSZ);
    cudaFuncSetAttribute(gemm_f16<512, 128, false, true, true, false, 1>,
                         cudaFuncAttributeMaxDynamicSharedMemorySize, (int)SMEMSZ);
    cudaFuncSetAttribute(gemm_f16<512, 128, false, true, true, false, 2>,
                         cudaFuncAttributeMaxDynamicSharedMemorySize, (int)SMEMSZ);
    cudaFuncSetAttribute(gemm_f16<256, 128, true, true, true, true, 1>,
                         cudaFuncAttributeMaxDynamicSharedMemorySize, (int)SMEMSZ);

    // side stream + events (created once; graph fork/join pattern)
    static cudaStream_t sB = nullptr;
    static cudaEvent_t evFork = nullptr, evJoin = nullptr;
    if (sB == nullptr) {
        cudaStreamCreateWithFlags(&sB, cudaStreamNonBlocking);
        cudaEventCreateWithFlags(&evFork, cudaEventDisableTiming);
        cudaEventCreateWithFlags(&evJoin, cudaEventDisableTiming);
    }

    // ---- parameter conversion tables ----
    PTab tabA; int na = 0;
    tabA.e[na++] = { t_in_w,  wqkv, 384, 128, 0 };
    tabA.e[na++] = { t_out_w, wout, 128, 128, 0 };
    tabA.e[na++] = { t_f_w1,  wf1,  512, 128, 0 };
    tabA.e[na++] = { t_f_w2,  wf2,  128, 512, 0 };
    tabA.e[na++] = { t_in_b,  bqkv, 1, 384, 1 };
    tabA.e[na++] = { t_out_b, bout, 1, 128, 1 };
    tabA.e[na++] = { t_f_b1,  bf1,  1, 512, 1 };
    tabA.e[na++] = { t_f_b2,  bf2,  1, 128, 1 };
    tabA.e[na++] = { ln1g, l1g, 1, 128, 1 };
    tabA.e[na++] = { ln1b, l1b, 1, 128, 1 };
    tabA.e[na++] = { ln2g, l2g, 1, 128, 1 };
    tabA.e[na++] = { ln2b, l2b, 1, 128, 1 };
    PTab tabB; int nb = 0;
    for (int i = 1; i < 3; i++) {
        tabB.e[nb++] = { t_in_w  + (size_t)i * 384 * 128, wqkv + (size_t)i * 384 * 128, 384, 128, 0 };
        tabB.e[nb++] = { t_out_w + (size_t)i * 128 * 128, wout + (size_t)i * 128 * 128, 128, 128, 0 };
        tabB.e[nb++] = { t_f_w1  + (size_t)i * 512 * 128, wf1  + (size_t)i * 512 * 128, 512, 128, 0 };
        tabB.e[nb++] = { t_f_w2  + (size_t)i * 128 * 512, wf2  + (size_t)i * 128 * 512, 128, 512, 0 };
        tabB.e[nb++] = { t_in_b  + i * 384, bqkv + i * 384, 1, 384, 1 };
        tabB.e[nb++] = { t_out_b + i * 128, bout + i * 128, 1, 128, 1 };
        tabB.e[nb++] = { t_f_b1  + i * 512, bf1  + i * 512, 1, 512, 1 };
        tabB.e[nb++] = { t_f_b2  + i * 128, bf2  + i * 128, 1, 128, 1 };
        tabB.e[nb++] = { ln1g + i * 128, l1g + i * 128, 1, 128, 1 };
        tabB.e[nb++] = { ln1b + i * 128, l1b + i * 128, 1, 128, 1 };
        tabB.e[nb++] = { ln2g + i * 128, l2g + i * 128, 1, 128, 1 };
        tabB.e[nb++] = { ln2b + i * 128, l2b + i * 128, 1, 128, 1 };
    }
    for (int i = 0; i < 2; i++) {
        tabB.e[nb++] = { gw + (size_t)i * 128 * 256, wg + (size_t)i * 128 * 256, 128, 256, 0 };
        tabB.e[nb++] = { gb   + i * 128, bg  + i * 128, 1, 128, 1 };
        tabB.e[nb++] = { glng + i * 128, gg  + i * 128, 1, 128, 1 };
        tabB.e[nb++] = { glnb + i * 128, gbv + i * 128, 1, 128, 1 };
    }

    // fork point: side work depends only on inputs
    cudaEventRecord(evFork, 0);
    cudaStreamWaitEvent(sB, evFork, 0);

    // ---- main stream: critical conversions + trans1 ----
    param_conv<<<dim3(64, na), 256>>>(tabA, na);
    conv_x<<<(NN * 128 + 255) / 256, 256>>>(x, phx);

    // ---- side stream: rest of params + CSR build (overlaps trans1) ----
    param_conv<<<dim3(64, nb), 256, 0, sB>>>(tabB, nb);
    zero_kernel<<<(n + 255) / 256, 256, 0, sB>>>(pdeg, pcnt, n);
    hist_kernel<<<EG, 256, 0, sB>>>(esrc, pdeg, e);
    scan1_kernel<<<SCAN_BLOCKS, 256, 0, sB>>>(pdeg, poff, pbsum, n);
    scan2_kernel<<<SCAN_BLOCKS, 256, 0, sB>>>(pbsum, poff, n);
    scatter_kernel<<<EG, 256, 0, sB>>>(esrc, edst, poff, pcnt, pcsr, e);
    cudaEventRecord(evJoin, sB);

    // ---- transformer layer ----
    auto run_trans = [&](const __half* hin, __half* hout, int i, bool final_layer) {
        gemm_f16<128, 384, false, false, false, false, 1><<<dim3(GX, 3), 256, SMEMSZ>>>(
            hin, nullptr, wqkv + (size_t)i * 384 * 128, bqkv + i * 384,
            nullptr, nullptr, nullptr, pqkv, nullptr, n);
        attn_kernel<<<WARP_GRID, 256>>>(pqkv, samples, pattn, n);
        gemm_f16<128, 128, false, true, true, false, 1><<<dim3(GX, 1), 256, SMEMSZ>>>(
            pattn, nullptr, wout + (size_t)i * 128 * 128, bout + i * 128,
            hin, l1g + i * 128, l1b + i * 128, pa, nullptr, n);
        gemm_f16<128, 512, true, false, false, false, 1><<<dim3(GX, 4), 256, SMEMSZ>>>(
            pa, nullptr, wf1 + (size_t)i * 512 * 128, bf1 + i * 512,
            nullptr, nullptr, nullptr, ptmp, nullptr, n);
        if (final_layer) {
            gemm_f16<512, 128, false, true, true, false, 2><<<dim3(GX, 1), 256, SMEMSZ>>>(
                ptmp, nullptr, wf2 + (size_t)i * 128 * 512, bf2 + i * 128,
                pa, l2g + i * 128, l2b + i * 128, nullptr, (float*)d_out, n);
        } else {
            gemm_f16<512, 128, false, true, true, false, 1><<<dim3(GX, 1), 256, SMEMSZ>>>(
                ptmp, nullptr, wf2 + (size_t)i * 128 * 512, bf2 + i * 128,
                pa, l2g + i * 128, l2b + i * 128, hout, nullptr, n);
        }
    };

    auto run_gnn = [&](const __half* hin, __half* hout, int i) {
        agg_kernel<<<WARP_GRID, 256>>>(hin, poff, pcsr, pneigh, n);
        gemm_f16<256, 128, true, true, true, true, 1><<<dim3(GX, 1), 256, SMEMSZ>>>(
            hin, pneigh, wg + (size_t)i * 128 * 256, bg + i * 128,
            hin, gg + i * 128, gbv + i * 128, hout, nullptr, n);
    };

    run_trans(phx, ph, 0, false);

    // join before first aggregation
    cudaStreamWaitEvent(0, evJoin, 0);

    run_gnn(ph, ph2, 0);
    run_trans(ph2, ph, 1, false);
    run_gnn(ph, ph2, 1);
    run_trans(ph2, nullptr, 2, true);
}